// round 3
// baseline (speedup 1.0000x reference)
#include <cuda_runtime.h>
#include <cstdint>
#include <cstddef>

// Problem constants
#define B_TOTAL 32768
#define T_STEPS 30
#define HDIM    384
#define BT      32      // batch rows per CTA
#define NTH     128     // threads per CTA
#define KTOT    512     // K of unified GEMM: [x(128) | hidden(384)]
#define NCOLS   1536    // N of unified GEMM: 384 h * 4 gates (r,z,s,hn)
#define KSLAB   8
#define NSLABS  (KTOT / KSLAB)   // 64
#define NCHUNK  12               // 1536 cols / 128 per chunk
#define D1      64
#define NSLABS2 (HDIM / KSLAB)   // 48

// ---- device scratch (no allocations allowed) ----
__device__ float g_Wpack[KTOT * NCOLS];     // [k][1536], gate-interleaved cols
__device__ float g_bias[NCOLS];
__device__ float g_Wd1T[HDIM * D1];         // [k][64]
__device__ float g_hidden[(size_t)B_TOTAL * HDIM];  // per-step staging

// ----------------------------------------------------------------------------
// Prep: pack W = [W_ih | W_hh] with column order col = 128*chunk + 4*i + g,
// h = 32*chunk + i, gates g: 0=r, 1=z, 2=s (combined inn+hn), 3=hn (zero-pad k<128)
// ----------------------------------------------------------------------------
__global__ void pack_kernel(const float* __restrict__ W_ih,
                            const float* __restrict__ W_hh,
                            const float* __restrict__ b_ih,
                            const float* __restrict__ b_hh,
                            const float* __restrict__ Wd1)
{
    int idx = blockIdx.x * blockDim.x + threadIdx.x;
    if (idx < KTOT * NCOLS) {
        int k = idx / NCOLS;
        int p = idx - k * NCOLS;
        int c = p >> 7;
        int q = p & 127;
        int i = q >> 2;
        int g = q & 3;
        int h = c * 32 + i;
        float v;
        if (g < 3) {
            int row = g * HDIM + h;   // g=2 -> row 768+h (n-gate, combined)
            v = (k < 128) ? W_ih[row * 128 + k] : W_hh[row * HDIM + (k - 128)];
        } else {
            v = (k < 128) ? 0.0f : W_hh[(2 * HDIM + h) * HDIM + (k - 128)];
        }
        g_Wpack[idx] = v;
    }
    if (idx < NCOLS) {
        int c = idx >> 7, q = idx & 127, i = q >> 2, g = q & 3;
        int h = c * 32 + i;
        float bv;
        if (g == 3) bv = b_hh[2 * HDIM + h];
        else        bv = b_ih[g * HDIM + h] + b_hh[g * HDIM + h];
        g_bias[idx] = bv;
    }
    if (idx < HDIM * D1) {
        int k = idx >> 6, j = idx & 63;
        g_Wd1T[idx] = Wd1[j * HDIM + k];
    }
}

// ---- cp.async helpers ----
__device__ __forceinline__ void cp16(float* dst, const float* src) {
    unsigned d = (unsigned)__cvta_generic_to_shared(dst);
    asm volatile("cp.async.ca.shared.global [%0], [%1], 16;\n" :: "r"(d), "l"(src));
}
__device__ __forceinline__ void cp_commit() {
    asm volatile("cp.async.commit_group;\n");
}
template<int N> __device__ __forceinline__ void cp_wait() {
    asm volatile("cp.async.wait_group %0;\n" :: "n"(N));
}

__device__ __forceinline__ float sigmoid_f(float x) {
    return 1.0f / (1.0f + __expf(-x));
}
__device__ __forceinline__ float tanh_f(float x) {
    // numerically safe for |x| large: exp->inf gives 1, exp->0 gives -1
    float e2 = __expf(2.0f * x);
    return 1.0f - 2.0f / (e2 + 1.0f);
}

// ----------------------------------------------------------------------------
// Persistent per-batch-tile decoder: each CTA owns BT=32 rows through T=30 steps
// ----------------------------------------------------------------------------
__global__ void __launch_bounds__(NTH, 3)
decoder_kernel(const float* __restrict__ init_hidden,
               const float* __restrict__ plan,
               const float* __restrict__ gate,
               const float* __restrict__ init_state,
               const float* __restrict__ Wp, const float* __restrict__ bp,
               const float* __restrict__ Ws, const float* __restrict__ bs,
               const float* __restrict__ Wd2, const float* __restrict__ bd2,
               const float* __restrict__ bd1,
               float* __restrict__ out)
{
    extern __shared__ float sm[];
    float* hs     = sm;                       // BT*HDIM = 12288 f
    float* xs     = hs + BT * HDIM;           // BT*128  = 4096 f (reused as d1 buf)
    float* slab   = xs + BT * 128;            // 2*KSLAB*128 = 2048 f
    float* plan_s = slab + 2 * KSLAB * 128;   // 96 f
    float* st_s   = plan_s + 96;              // 96 f
    float* gate_s = st_s + 96;                // 32 f

    const int tid  = threadIdx.x;
    const int lane = tid & 31;
    const int warp = tid >> 5;
    const int b0   = warp * 8;                // each warp owns 8 batch rows
    const int bg0  = blockIdx.x * BT;

    // ---- init ----
    for (int i = tid; i < BT * HDIM; i += NTH)
        hs[i] = init_hidden[(size_t)bg0 * HDIM + i];
    if (tid < BT * 3) st_s[tid] = init_state[bg0 * 3 + tid];
    if (tid < BT)     gate_s[tid] = gate[bg0 + tid];

    // per-thread x-projection params (thread tid owns column j = tid of x)
    const float ws0 = Ws[tid * 3 + 0], ws1 = Ws[tid * 3 + 1], ws2 = Ws[tid * 3 + 2];
    const float wp0 = Wp[tid * 3 + 0], wp1 = Wp[tid * 3 + 1], wp2 = Wp[tid * 3 + 2];
    const float bsj = bs[tid], bpj = bp[tid];
    __syncthreads();

    // slab-copy mapping (main GEMM): thread copies 2 consecutive float4s
    const int f    = tid * 2;
    const int srow = f >> 5;          // 0..7
    const int scol = (f & 31) << 2;   // 0..120 (pairs cover 128 cols)
    // slab-copy mapping (decode GEMM): thread copies 1 float4 of an 8x64 slab
    const int drow = tid >> 4;        // 0..7
    const int dcol = (tid & 15) << 2; // 0..60

    for (int t = 0; t < T_STEPS; ++t) {
        // ---- stage plan_t ----
        if (tid < BT * 3) {
            int b = tid / 3, j = tid - b * 3;
            plan_s[tid] = plan[(size_t)(bg0 + b) * (T_STEPS * 3) + t * 3 + j];
        }
        __syncthreads();

        // ---- x = state@Ws^T + bs + gate*(plan@Wp^T + bp) ----
        #pragma unroll 4
        for (int b = 0; b < BT; ++b) {
            float v = bsj + ws0 * st_s[b * 3] + ws1 * st_s[b * 3 + 1] + ws2 * st_s[b * 3 + 2]
                    + gate_s[b] * (bpj + wp0 * plan_s[b * 3] + wp1 * plan_s[b * 3 + 1]
                                       + wp2 * plan_s[b * 3 + 2]);
            xs[b * 128 + tid] = v;
        }
        __syncthreads();

        // ---- unified gate GEMM: [BT x 512] * [512 x 1536], in 12 col-chunks ----
        for (int c = 0; c < NCHUNK; ++c) {
            const float* wbase = g_Wpack + c * 128;
            float4 bias4 = *reinterpret_cast<const float4*>(&g_bias[c * 128 + (lane << 2)]);
            float acc[8][4];
            #pragma unroll
            for (int r = 0; r < 8; ++r) {
                acc[r][0] = bias4.x; acc[r][1] = bias4.y;
                acc[r][2] = bias4.z; acc[r][3] = bias4.w;
            }

            // prologue: slab 0
            cp16(&slab[srow * 128 + scol],     wbase + (size_t)srow * NCOLS + scol);
            cp16(&slab[srow * 128 + scol + 4], wbase + (size_t)srow * NCOLS + scol + 4);
            cp_commit();

            for (int s = 0; s < NSLABS; ++s) {
                if (s + 1 < NSLABS) {
                    const float* src = wbase + (size_t)(s + 1) * KSLAB * NCOLS;
                    float* dst = slab + ((s + 1) & 1) * (KSLAB * 128);
                    cp16(&dst[srow * 128 + scol],     src + (size_t)srow * NCOLS + scol);
                    cp16(&dst[srow * 128 + scol + 4], src + (size_t)srow * NCOLS + scol + 4);
                    cp_commit();
                    cp_wait<1>();
                } else {
                    cp_wait<0>();
                }
                __syncthreads();

                const float* sl = slab + (s & 1) * (KSLAB * 128);
                const bool in_x = (s < 128 / KSLAB);
                const float* A  = in_x ? (xs + b0 * 128) : (hs + b0 * HDIM);
                const int astride = in_x ? 128 : HDIM;
                const int kb = in_x ? (s * KSLAB) : (s * KSLAB - 128);

                #pragma unroll
                for (int kk = 0; kk < KSLAB; ++kk) {
                    float4 wv = *reinterpret_cast<const float4*>(&sl[kk * 128 + (lane << 2)]);
                    #pragma unroll
                    for (int r = 0; r < 8; ++r) {
                        float a = A[r * astride + kb + kk];   // warp-broadcast LDS
                        acc[r][0] = fmaf(a, wv.x, acc[r][0]);
                        acc[r][1] = fmaf(a, wv.y, acc[r][1]);
                        acc[r][2] = fmaf(a, wv.z, acc[r][2]);
                        acc[r][3] = fmaf(a, wv.w, acc[r][3]);
                    }
                }
                __syncthreads();
            }

            // ---- GRU pointwise for h = c*32 + lane, 8 rows ----
            const int h = c * 32 + lane;
            #pragma unroll
            for (int r = 0; r < 8; ++r) {
                float oldh = hs[(b0 + r) * HDIM + h];
                float rg = sigmoid_f(acc[r][0]);
                float zg = sigmoid_f(acc[r][1]);
                // s-col = inn+hn (both biases), hn-col = hn (b_hh bias):
                // n_pre = inn + r*hn = s + (r-1)*hn
                float ng = tanh_f(acc[r][2] + (rg - 1.0f) * acc[r][3]);
                float nh = (1.0f - zg) * ng + zg * oldh;
                g_hidden[(size_t)(bg0 + b0 + r) * HDIM + h] = nh;   // stage new hidden
            }
        }
        __syncthreads();

        // ---- pull new hidden back into smem (old hs no longer needed) ----
        for (int i = tid; i < BT * HDIM; i += NTH)
            hs[i] = g_hidden[(size_t)bg0 * HDIM + i];
        __syncthreads();

        // ---- decode layer 1: d1 = elu(hidden @ Wd1^T + bd1), [BT x 64], K=384 ----
        {
            float acc2[8][2];
            const float bb0 = bd1[lane * 2], bb1 = bd1[lane * 2 + 1];
            #pragma unroll
            for (int r = 0; r < 8; ++r) { acc2[r][0] = bb0; acc2[r][1] = bb1; }

            cp16(&slab[drow * 64 + dcol], g_Wd1T + (size_t)drow * D1 + dcol);
            cp_commit();

            for (int s = 0; s < NSLABS2; ++s) {
                if (s + 1 < NSLABS2) {
                    float* dst = slab + ((s + 1) & 1) * (KSLAB * 128);
                    cp16(&dst[drow * 64 + dcol],
                         g_Wd1T + (size_t)((s + 1) * KSLAB + drow) * D1 + dcol);
                    cp_commit();
                    cp_wait<1>();
                } else {
                    cp_wait<0>();
                }
                __syncthreads();
                const float* sl = slab + (s & 1) * (KSLAB * 128);
                #pragma unroll
                for (int kk = 0; kk < KSLAB; ++kk) {
                    float2 wv = *reinterpret_cast<const float2*>(&sl[kk * 64 + (lane << 1)]);
                    #pragma unroll
                    for (int r = 0; r < 8; ++r) {
                        float a = hs[(b0 + r) * HDIM + s * KSLAB + kk];
                        acc2[r][0] = fmaf(a, wv.x, acc2[r][0]);
                        acc2[r][1] = fmaf(a, wv.y, acc2[r][1]);
                    }
                }
                __syncthreads();
            }

            // ELU, store d1 into xs region (free until next step's x)
            #pragma unroll
            for (int r = 0; r < 8; ++r) {
                float v0 = acc2[r][0], v1 = acc2[r][1];
                v0 = v0 > 0.0f ? v0 : (__expf(v0) - 1.0f);
                v1 = v1 > 0.0f ? v1 : (__expf(v1) - 1.0f);
                xs[(b0 + r) * 64 + lane * 2]     = v0;
                xs[(b0 + r) * 64 + lane * 2 + 1] = v1;
            }
        }
        __syncthreads();

        // ---- decode layer 2 + state update + output write ----
        if (tid < BT * 3) {
            int b = tid / 3, j = tid - b * 3;
            const float* w = Wd2 + j * 64;
            const float* d = xs + b * 64;
            float sum = bd2[j];
            #pragma unroll
            for (int k = 0; k < 64; ++k)
                sum = fmaf(d[k], __ldg(&w[k]), sum);
            float ns = st_s[tid] + sum;
            st_s[tid] = ns;
            out[(size_t)(bg0 + b) * (T_STEPS * 3) + t * 3 + j] = ns;
        }
        __syncthreads();
    }
}

// ----------------------------------------------------------------------------
extern "C" void kernel_launch(void* const* d_in, const int* in_sizes, int n_in,
                              void* d_out, int out_size)
{
    (void)in_sizes; (void)n_in; (void)out_size;
    const float* init_hidden = (const float*)d_in[0];
    const float* plan        = (const float*)d_in[1];
    const float* gate        = (const float*)d_in[2];
    const float* init_state  = (const float*)d_in[3];
    const float* Wp   = (const float*)d_in[4];
    const float* bp   = (const float*)d_in[5];
    const float* Ws   = (const float*)d_in[6];
    const float* bs   = (const float*)d_in[7];
    const float* W_ih = (const float*)d_in[8];
    const float* b_ih = (const float*)d_in[9];
    const float* W_hh = (const float*)d_in[10];
    const float* b_hh = (const float*)d_in[11];
    const float* Wd1  = (const float*)d_in[12];
    const float* bd1  = (const float*)d_in[13];
    const float* Wd2  = (const float*)d_in[14];
    const float* bd2  = (const float*)d_in[15];
    float* out = (float*)d_out;

    pack_kernel<<<(KTOT * NCOLS + 255) / 256, 256>>>(W_ih, W_hh, b_ih, b_hh, Wd1);

    const int smem_bytes = (BT * HDIM + BT * 128 + 2 * KSLAB * 128 + 96 + 96 + 32) * 4;
    cudaFuncSetAttribute(decoder_kernel,
                         cudaFuncAttributeMaxDynamicSharedMemorySize, smem_bytes);
    decoder_kernel<<<B_TOTAL / BT, NTH, smem_bytes>>>(
        init_hidden, plan, gate, init_state,
        Wp, bp, Ws, bs, Wd2, bd2, bd1, out);
}

// round 4
// speedup vs baseline: 1.0576x; 1.0576x over previous
#include <cuda_runtime.h>
#include <cstdint>
#include <cstddef>

// Problem constants
#define B_TOTAL 32768
#define T_STEPS 30
#define HDIM    384
#define BT      32      // batch rows per CTA
#define NTH     128     // threads per CTA
#define KTOT    512     // K of unified GEMM: [x(128) | hidden(384)]
#define NCOLS   1536    // N of unified GEMM: 384 h * 4 gates (r,z,s,hn)
#define KSLAB   8
#define NSLABS  (KTOT / KSLAB)   // 64
#define NCHUNK  12               // 1536 cols / 128 per chunk
#define D1      64
#define NSLABS2 (HDIM / KSLAB)   // 48

// ---- device scratch (no allocations allowed) ----
__device__ float g_Wpack[KTOT * NCOLS];     // [k][1536], gate-interleaved cols
__device__ float g_bias[NCOLS];
__device__ float g_Wd1T[HDIM * D1];         // [k][64]
__device__ float g_hidden[(size_t)B_TOTAL * HDIM];  // per-step staging

// ----------------------------------------------------------------------------
// Prep: pack W = [W_ih | W_hh] with column order col = 128*chunk + 4*i + g,
// h = 32*chunk + i, gates g: 0=r, 1=z, 2=s (combined inn+hn), 3=hn (zero-pad k<128)
// ----------------------------------------------------------------------------
__global__ void pack_kernel(const float* __restrict__ W_ih,
                            const float* __restrict__ W_hh,
                            const float* __restrict__ b_ih,
                            const float* __restrict__ b_hh,
                            const float* __restrict__ Wd1)
{
    int idx = blockIdx.x * blockDim.x + threadIdx.x;
    if (idx < KTOT * NCOLS) {
        int k = idx / NCOLS;
        int p = idx - k * NCOLS;
        int c = p >> 7;
        int q = p & 127;
        int i = q >> 2;
        int g = q & 3;
        int h = c * 32 + i;
        float v;
        if (g < 3) {
            int row = g * HDIM + h;   // g=2 -> row 768+h (n-gate, combined)
            v = (k < 128) ? W_ih[row * 128 + k] : W_hh[row * HDIM + (k - 128)];
        } else {
            v = (k < 128) ? 0.0f : W_hh[(2 * HDIM + h) * HDIM + (k - 128)];
        }
        g_Wpack[idx] = v;
    }
    if (idx < NCOLS) {
        int c = idx >> 7, q = idx & 127, i = q >> 2, g = q & 3;
        int h = c * 32 + i;
        float bv;
        if (g == 3) bv = b_hh[2 * HDIM + h];
        else        bv = b_ih[g * HDIM + h] + b_hh[g * HDIM + h];
        g_bias[idx] = bv;
    }
    if (idx < HDIM * D1) {
        int k = idx >> 6, j = idx & 63;
        g_Wd1T[idx] = Wd1[j * HDIM + k];
    }
}

// ---- cp.async helpers ----
__device__ __forceinline__ void cp16(float* dst, const float* src) {
    unsigned d = (unsigned)__cvta_generic_to_shared(dst);
    asm volatile("cp.async.ca.shared.global [%0], [%1], 16;\n" :: "r"(d), "l"(src));
}
__device__ __forceinline__ void cp_commit() {
    asm volatile("cp.async.commit_group;\n");
}
template<int N> __device__ __forceinline__ void cp_wait() {
    asm volatile("cp.async.wait_group %0;\n" :: "n"(N));
}

__device__ __forceinline__ float sigmoid_f(float x) {
    return 1.0f / (1.0f + __expf(-x));
}
__device__ __forceinline__ float tanh_f(float x) {
    // numerically safe for |x| large: exp->inf gives 1, exp->0 gives -1
    float e2 = __expf(2.0f * x);
    return 1.0f - 2.0f / (e2 + 1.0f);
}

// ----------------------------------------------------------------------------
// Persistent per-batch-tile decoder: each CTA owns BT=32 rows through T=30 steps
// ----------------------------------------------------------------------------
__global__ void __launch_bounds__(NTH, 3)
decoder_kernel(const float* __restrict__ init_hidden,
               const float* __restrict__ plan,
               const float* __restrict__ gate,
               const float* __restrict__ init_state,
               const float* __restrict__ Wp, const float* __restrict__ bp,
               const float* __restrict__ Ws, const float* __restrict__ bs,
               const float* __restrict__ Wd2, const float* __restrict__ bd2,
               const float* __restrict__ bd1,
               float* __restrict__ out)
{
    extern __shared__ float sm[];
    float* hs     = sm;                       // BT*HDIM = 12288 f
    float* xs     = hs + BT * HDIM;           // BT*128  = 4096 f (reused as d1 buf)
    float* slab   = xs + BT * 128;            // 2*KSLAB*128 = 2048 f
    float* plan_s = slab + 2 * KSLAB * 128;   // 96 f
    float* st_s   = plan_s + 96;              // 96 f
    float* gate_s = st_s + 96;                // 32 f

    const int tid  = threadIdx.x;
    const int lane = tid & 31;
    const int warp = tid >> 5;
    const int b0   = warp * 8;                // each warp owns 8 batch rows
    const int bg0  = blockIdx.x * BT;

    // ---- init ----
    for (int i = tid; i < BT * HDIM; i += NTH)
        hs[i] = init_hidden[(size_t)bg0 * HDIM + i];
    if (tid < BT * 3) st_s[tid] = init_state[bg0 * 3 + tid];
    if (tid < BT)     gate_s[tid] = gate[bg0 + tid];

    // per-thread x-projection params (thread tid owns column j = tid of x)
    const float ws0 = Ws[tid * 3 + 0], ws1 = Ws[tid * 3 + 1], ws2 = Ws[tid * 3 + 2];
    const float wp0 = Wp[tid * 3 + 0], wp1 = Wp[tid * 3 + 1], wp2 = Wp[tid * 3 + 2];
    const float bsj = bs[tid], bpj = bp[tid];
    __syncthreads();

    // slab-copy mapping (main GEMM): thread copies 2 consecutive float4s
    const int f    = tid * 2;
    const int srow = f >> 5;          // 0..7
    const int scol = (f & 31) << 2;   // 0..120 (pairs cover 128 cols)
    // slab-copy mapping (decode GEMM): thread copies 1 float4 of an 8x64 slab
    const int drow = tid >> 4;        // 0..7
    const int dcol = (tid & 15) << 2; // 0..60

    for (int t = 0; t < T_STEPS; ++t) {
        // ---- stage plan_t ----
        if (tid < BT * 3) {
            int b = tid / 3, j = tid - b * 3;
            plan_s[tid] = plan[(size_t)(bg0 + b) * (T_STEPS * 3) + t * 3 + j];
        }
        __syncthreads();

        // ---- x = state@Ws^T + bs + gate*(plan@Wp^T + bp) ----
        #pragma unroll 4
        for (int b = 0; b < BT; ++b) {
            float v = bsj + ws0 * st_s[b * 3] + ws1 * st_s[b * 3 + 1] + ws2 * st_s[b * 3 + 2]
                    + gate_s[b] * (bpj + wp0 * plan_s[b * 3] + wp1 * plan_s[b * 3 + 1]
                                       + wp2 * plan_s[b * 3 + 2]);
            xs[b * 128 + tid] = v;
        }
        __syncthreads();

        // ---- unified gate GEMM: [BT x 512] * [512 x 1536], in 12 col-chunks ----
        for (int c = 0; c < NCHUNK; ++c) {
            const float* wbase = g_Wpack + c * 128;
            float4 bias4 = *reinterpret_cast<const float4*>(&g_bias[c * 128 + (lane << 2)]);
            float acc[8][4];
            #pragma unroll
            for (int r = 0; r < 8; ++r) {
                acc[r][0] = bias4.x; acc[r][1] = bias4.y;
                acc[r][2] = bias4.z; acc[r][3] = bias4.w;
            }

            // prologue: slab 0
            cp16(&slab[srow * 128 + scol],     wbase + (size_t)srow * NCOLS + scol);
            cp16(&slab[srow * 128 + scol + 4], wbase + (size_t)srow * NCOLS + scol + 4);
            cp_commit();

            for (int s = 0; s < NSLABS; ++s) {
                if (s + 1 < NSLABS) {
                    const float* src = wbase + (size_t)(s + 1) * KSLAB * NCOLS;
                    float* dst = slab + ((s + 1) & 1) * (KSLAB * 128);
                    cp16(&dst[srow * 128 + scol],     src + (size_t)srow * NCOLS + scol);
                    cp16(&dst[srow * 128 + scol + 4], src + (size_t)srow * NCOLS + scol + 4);
                    cp_commit();
                    cp_wait<1>();
                } else {
                    cp_wait<0>();
                }
                __syncthreads();

                const float* sl = slab + (s & 1) * (KSLAB * 128);
                const bool in_x = (s < 128 / KSLAB);
                const float* A  = in_x ? (xs + b0 * 128) : (hs + b0 * HDIM);
                const int astride = in_x ? 128 : HDIM;
                const int kb = in_x ? (s * KSLAB) : (s * KSLAB - 128);

                #pragma unroll
                for (int kk = 0; kk < KSLAB; ++kk) {
                    float4 wv = *reinterpret_cast<const float4*>(&sl[kk * 128 + (lane << 2)]);
                    #pragma unroll
                    for (int r = 0; r < 8; ++r) {
                        float a = A[r * astride + kb + kk];   // warp-broadcast LDS
                        acc[r][0] = fmaf(a, wv.x, acc[r][0]);
                        acc[r][1] = fmaf(a, wv.y, acc[r][1]);
                        acc[r][2] = fmaf(a, wv.z, acc[r][2]);
                        acc[r][3] = fmaf(a, wv.w, acc[r][3]);
                    }
                }
                __syncthreads();
            }

            // ---- GRU pointwise for h = c*32 + lane, 8 rows ----
            const int h = c * 32 + lane;
            #pragma unroll
            for (int r = 0; r < 8; ++r) {
                float oldh = hs[(b0 + r) * HDIM + h];
                float rg = sigmoid_f(acc[r][0]);
                float zg = sigmoid_f(acc[r][1]);
                // s-col = inn+hn (both biases), hn-col = hn (b_hh bias):
                // n_pre = inn + r*hn = s + (r-1)*hn
                float ng = tanh_f(acc[r][2] + (rg - 1.0f) * acc[r][3]);
                float nh = (1.0f - zg) * ng + zg * oldh;
                g_hidden[(size_t)(bg0 + b0 + r) * HDIM + h] = nh;   // stage new hidden
            }
        }
        __syncthreads();

        // ---- pull new hidden back into smem (old hs no longer needed) ----
        for (int i = tid; i < BT * HDIM; i += NTH)
            hs[i] = g_hidden[(size_t)bg0 * HDIM + i];
        __syncthreads();

        // ---- decode layer 1: d1 = elu(hidden @ Wd1^T + bd1), [BT x 64], K=384 ----
        {
            float acc2[8][2];
            const float bb0 = bd1[lane * 2], bb1 = bd1[lane * 2 + 1];
            #pragma unroll
            for (int r = 0; r < 8; ++r) { acc2[r][0] = bb0; acc2[r][1] = bb1; }

            cp16(&slab[drow * 64 + dcol], g_Wd1T + (size_t)drow * D1 + dcol);
            cp_commit();

            for (int s = 0; s < NSLABS2; ++s) {
                if (s + 1 < NSLABS2) {
                    float* dst = slab + ((s + 1) & 1) * (KSLAB * 128);
                    cp16(&dst[drow * 64 + dcol],
                         g_Wd1T + (size_t)((s + 1) * KSLAB + drow) * D1 + dcol);
                    cp_commit();
                    cp_wait<1>();
                } else {
                    cp_wait<0>();
                }
                __syncthreads();
                const float* sl = slab + (s & 1) * (KSLAB * 128);
                #pragma unroll
                for (int kk = 0; kk < KSLAB; ++kk) {
                    float2 wv = *reinterpret_cast<const float2*>(&sl[kk * 64 + (lane << 1)]);
                    #pragma unroll
                    for (int r = 0; r < 8; ++r) {
                        float a = hs[(b0 + r) * HDIM + s * KSLAB + kk];
                        acc2[r][0] = fmaf(a, wv.x, acc2[r][0]);
                        acc2[r][1] = fmaf(a, wv.y, acc2[r][1]);
                    }
                }
                __syncthreads();
            }

            // ELU, store d1 into xs region (free until next step's x)
            #pragma unroll
            for (int r = 0; r < 8; ++r) {
                float v0 = acc2[r][0], v1 = acc2[r][1];
                v0 = v0 > 0.0f ? v0 : (__expf(v0) - 1.0f);
                v1 = v1 > 0.0f ? v1 : (__expf(v1) - 1.0f);
                xs[(b0 + r) * 64 + lane * 2]     = v0;
                xs[(b0 + r) * 64 + lane * 2 + 1] = v1;
            }
        }
        __syncthreads();

        // ---- decode layer 2 + state update + output write ----
        if (tid < BT * 3) {
            int b = tid / 3, j = tid - b * 3;
            const float* w = Wd2 + j * 64;
            const float* d = xs + b * 64;
            float sum = bd2[j];
            #pragma unroll
            for (int k = 0; k < 64; ++k)
                sum = fmaf(d[k], __ldg(&w[k]), sum);
            float ns = st_s[tid] + sum;
            st_s[tid] = ns;
            out[(size_t)(bg0 + b) * (T_STEPS * 3) + t * 3 + j] = ns;
        }
        __syncthreads();
    }
}

// ----------------------------------------------------------------------------
extern "C" void kernel_launch(void* const* d_in, const int* in_sizes, int n_in,
                              void* d_out, int out_size)
{
    (void)in_sizes; (void)n_in; (void)out_size;
    const float* init_hidden = (const float*)d_in[0];
    const float* plan        = (const float*)d_in[1];
    const float* gate        = (const float*)d_in[2];
    const float* init_state  = (const float*)d_in[3];
    const float* Wp   = (const float*)d_in[4];
    const float* bp   = (const float*)d_in[5];
    const float* Ws   = (const float*)d_in[6];
    const float* bs   = (const float*)d_in[7];
    const float* W_ih = (const float*)d_in[8];
    const float* b_ih = (const float*)d_in[9];
    const float* W_hh = (const float*)d_in[10];
    const float* b_hh = (const float*)d_in[11];
    const float* Wd1  = (const float*)d_in[12];
    const float* bd1  = (const float*)d_in[13];
    const float* Wd2  = (const float*)d_in[14];
    const float* bd2  = (const float*)d_in[15];
    float* out = (float*)d_out;

    pack_kernel<<<(KTOT * NCOLS + 255) / 256, 256>>>(W_ih, W_hh, b_ih, b_hh, Wd1);

    const int smem_bytes = (BT * HDIM + BT * 128 + 2 * KSLAB * 128 + 96 + 96 + 32) * 4;
    cudaFuncSetAttribute(decoder_kernel,
                         cudaFuncAttributeMaxDynamicSharedMemorySize, smem_bytes);
    decoder_kernel<<<B_TOTAL / BT, NTH, smem_bytes>>>(
        init_hidden, plan, gate, init_state,
        Wp, bp, Ws, bs, Wd2, bd2, bd1, out);
}

// round 6
// speedup vs baseline: 1.6100x; 1.5224x over previous
#include <cuda_runtime.h>
#include <cuda_bf16.h>
#include <cstdint>
#include <cstddef>

// ---------------- problem constants ----------------
#define B_TOTAL 32768
#define T_STEPS 30
#define HDIM    384
#define BT      64          // batch rows per CTA
#define NTH     256         // 8 warps
#define KTOT    512         // [x(128) | hidden(384)]
#define NCOLS   1536        // 384 h * 4 gates (r,z,s,hn), gate-interleaved
#define NCHUNK  12          // 128 cols per chunk
#define SLAB_U32 4096       // 16KB: one slab = 2 ksteps(32 k) x 128 cols, hi+lo
#define MAIN_SLABS 192      // 12 chunks * 16 slabs
#define DEC_SLABS  12       // decode K=384 -> 12 slabs of 2 ksteps
#define DSLAB_U32  2048     // 8KB per decode slab
#define AROW32  260         // u32 per A row (256 used + 4 pad; 260%32==4 -> conflict-free)
#define D1      64
#define D1PAD   65
#define A_U32   (BT * AROW32)

// ---------------- device scratch (no allocations allowed) ----------------
__device__ uint32_t g_Wf[(size_t)MAIN_SLABS * SLAB_U32];   // 3 MB main-W frags (hi|lo)
__device__ uint32_t g_Wd1f[DEC_SLABS * DSLAB_U32];         // 96 KB Wd1 frags
__device__ float    g_bias[NCOLS];
__device__ float    g_hidden[(size_t)B_TOTAL * HDIM];      // fp32 recurrent state

// ---------------- helpers ----------------
__device__ __forceinline__ void cp16s(void* dst, const void* src) {
    unsigned d = (unsigned)__cvta_generic_to_shared(dst);
    asm volatile("cp.async.ca.shared.global [%0], [%1], 16;\n" :: "r"(d), "l"(src));
}
__device__ __forceinline__ void cp_commit() { asm volatile("cp.async.commit_group;\n"); }
template<int N> __device__ __forceinline__ void cp_wait() {
    asm volatile("cp.async.wait_group %0;\n" :: "n"(N));
}
__device__ __forceinline__ float sigmoid_f(float x) { return 1.0f / (1.0f + __expf(-x)); }
__device__ __forceinline__ float tanh_f(float x) {
    float e2 = __expf(2.0f * x);
    return 1.0f - 2.0f / (e2 + 1.0f);
}
__device__ __forceinline__ float elu_f(float x) {
    return x > 0.0f ? x : (__expf(x) - 1.0f);
}
__device__ __forceinline__ void mma16816(float* c,
    uint32_t a0, uint32_t a1, uint32_t a2, uint32_t a3, uint32_t b0, uint32_t b1)
{
    asm volatile(
        "mma.sync.aligned.m16n8k16.row.col.f32.bf16.bf16.f32 "
        "{%0,%1,%2,%3}, {%4,%5,%6,%7}, {%8,%9}, {%0,%1,%2,%3};\n"
        : "+f"(c[0]), "+f"(c[1]), "+f"(c[2]), "+f"(c[3])
        : "r"(a0), "r"(a1), "r"(a2), "r"(a3), "r"(b0), "r"(b1));
}
// split fp32x4 into hi/lo bf16x4 and store as two uint2 (u32-index destinations)
__device__ __forceinline__ void split_store4(uint32_t* hiw, uint32_t* low, float4 v) {
    float a[4] = {v.x, v.y, v.z, v.w};
    unsigned short hu[4], lu[4];
    #pragma unroll
    for (int u = 0; u < 4; ++u) {
        __nv_bfloat16 h = __float2bfloat16(a[u]);
        hu[u] = __bfloat16_as_ushort(h);
        lu[u] = __bfloat16_as_ushort(__float2bfloat16(a[u] - __bfloat162float(h)));
    }
    uint2 hw, lw;
    hw.x = (uint32_t)hu[0] | ((uint32_t)hu[1] << 16);
    hw.y = (uint32_t)hu[2] | ((uint32_t)hu[3] << 16);
    lw.x = (uint32_t)lu[0] | ((uint32_t)lu[1] << 16);
    lw.y = (uint32_t)lu[2] | ((uint32_t)lu[3] << 16);
    *reinterpret_cast<uint2*>(hiw) = hw;
    *reinterpret_cast<uint2*>(low) = lw;
}

// ----------------------------------------------------------------------------
// Pack: W = [W_ih | W_hh] -> bf16 hi/lo in m16n8k16 B-fragment order.
// Main cols: col = 128*chunk + q; q&3 = gate g (0=r,1=z,2=s(inn+hn rows),3=hn,
// zero-padded k<128); q>>2 = i; h = chunk*32 + i. Fragment addressing:
// kstep=k>>4, kk=k&15, reg=kk>>3, tg2=(kk&7)>>1, half=kk&1, ntg=q>>3, n=q&7,
// lane=n*4+tg2, fragidx=ntg*64+lane*2+reg.  Slab base (u32): (chunk*32+kstep)*2048,
// hi at [base+fragidx], lo at [base+1024+fragidx], bf16 elem = u32*2+half.
// ----------------------------------------------------------------------------
__global__ void pack_kernel(const float* __restrict__ W_ih,
                            const float* __restrict__ W_hh,
                            const float* __restrict__ b_ih,
                            const float* __restrict__ b_hh,
                            const float* __restrict__ Wd1)
{
    int idx = blockIdx.x * blockDim.x + threadIdx.x;
    __nv_bfloat16* Wf16   = (__nv_bfloat16*)g_Wf;
    __nv_bfloat16* Wd1f16 = (__nv_bfloat16*)g_Wd1f;

    if (idx < KTOT * NCOLS) {
        int k = idx / NCOLS;
        int col = idx - k * NCOLS;
        int chunk = col >> 7, q = col & 127;
        int i = q >> 2, g = q & 3, h = chunk * 32 + i;
        float v;
        if (g < 3) {
            int row = g * HDIM + h;
            v = (k < 128) ? W_ih[row * 128 + k] : W_hh[row * HDIM + (k - 128)];
        } else {
            v = (k < 128) ? 0.0f : W_hh[(2 * HDIM + h) * HDIM + (k - 128)];
        }
        __nv_bfloat16 hi = __float2bfloat16(v);
        __nv_bfloat16 lo = __float2bfloat16(v - __bfloat162float(hi));
        int kstep = k >> 4, kk = k & 15;
        int reg = kk >> 3, tg2 = (kk & 7) >> 1, half = kk & 1;
        int ntg = q >> 3, n = q & 7;
        int lane = n * 4 + tg2;
        int fragidx = ntg * 64 + lane * 2 + reg;
        size_t base = (size_t)(chunk * 32 + kstep) * 2048;
        Wf16[(base + fragidx) * 2 + half]        = hi;
        Wf16[(base + 1024 + fragidx) * 2 + half] = lo;
    }
    if (idx < HDIM * D1) {     // Wd1 [64][384] -> frags; per kstep base = kstep*1024
        int k = idx >> 6, j = idx & 63;
        float v = Wd1[j * HDIM + k];
        __nv_bfloat16 hi = __float2bfloat16(v);
        __nv_bfloat16 lo = __float2bfloat16(v - __bfloat162float(hi));
        int kstep = k >> 4, kk = k & 15;
        int reg = kk >> 3, tg2 = (kk & 7) >> 1, half = kk & 1;
        int ntg = j >> 3, n = j & 7;
        int lane = n * 4 + tg2;
        int fragidx = ntg * 64 + lane * 2 + reg;
        size_t base = (size_t)kstep * 1024;
        Wd1f16[(base + fragidx) * 2 + half]       = hi;
        Wd1f16[(base + 512 + fragidx) * 2 + half] = lo;
    }
    if (idx < NCOLS) {
        int c = idx >> 7, q = idx & 127, i = q >> 2, g = q & 3;
        int h = c * 32 + i;
        float bv;
        if (g == 3) bv = b_hh[2 * HDIM + h];
        else        bv = b_ih[g * HDIM + h] + b_hh[g * HDIM + h];
        g_bias[idx] = bv;
    }
}

// ----------------------------------------------------------------------------
// Persistent per-tile decoder: 64 batch rows, split-bf16 tensor-core GEMMs.
// Warps: mw = warp&1 (32 rows, 2 mtiles of 16), nw = warp>>1 (32 cols, 4 ntiles).
// ----------------------------------------------------------------------------
__global__ void __launch_bounds__(NTH, 1)
decoder_kernel(const float* __restrict__ init_hidden,
               const float* __restrict__ plan,
               const float* __restrict__ gate,
               const float* __restrict__ init_state,
               const float* __restrict__ Wp, const float* __restrict__ bp,
               const float* __restrict__ Ws, const float* __restrict__ bs,
               const float* __restrict__ Wd2, const float* __restrict__ bd2,
               const float* __restrict__ bd1,
               float* __restrict__ out)
{
    extern __shared__ uint32_t sm32[];
    uint32_t* A_hi = sm32;                         // 16640 u32
    uint32_t* A_lo = A_hi + A_U32;                 // 16640
    uint32_t* wbuf = A_lo + A_U32;                 // 3*4096 = 12288
    float* d1s    = (float*)(wbuf + 3 * SLAB_U32); // 64*65 = 4160
    float* bias_s = d1s + BT * D1PAD;              // 1536
    float* bd1_s  = bias_s + NCOLS;                // 64
    float* wd2_s  = bd1_s + D1;                    // 192
    float* bd2_s  = wd2_s + 192;                   // 4
    float* plan_s = bd2_s + 4;                     // 192
    float* st_s   = plan_s + BT * 3;               // 192
    float* gate_s = st_s + BT * 3;                 // 64

    __nv_bfloat16* Ahi16 = (__nv_bfloat16*)A_hi;
    __nv_bfloat16* Alo16 = (__nv_bfloat16*)A_lo;

    const int tid  = threadIdx.x;
    const int lane = tid & 31;
    const int warp = tid >> 5;
    const int gid  = lane >> 2;      // 0..7
    const int tg   = lane & 3;       // 0..3
    const int mw   = warp & 1;       // 32-row half
    const int nw   = warp >> 1;      // 32-col quarter of 128-chunk
    const int bg0  = blockIdx.x * BT;

    // ---- stage constants ----
    for (int i = tid; i < NCOLS; i += NTH) bias_s[i] = g_bias[i];
    if (tid < D1)  bd1_s[tid] = bd1[tid];
    if (tid < 192) wd2_s[tid] = Wd2[tid];
    if (tid < 3)   bd2_s[tid] = bd2[tid];
    if (tid < BT * 3) st_s[tid] = init_state[bg0 * 3 + tid];
    if (tid < BT)     gate_s[tid] = gate[bg0 + tid];

    // ---- init hidden: fp32 -> g_hidden and hi/lo -> A smem ----
    {
        const float4* src = (const float4*)(init_hidden + (size_t)bg0 * HDIM);
        float4* gh = (float4*)(g_hidden + (size_t)bg0 * HDIM);
        for (int i = tid; i < BT * HDIM / 4; i += NTH) {
            float4 v = src[i];
            gh[i] = v;
            int r = i / (HDIM / 4);
            int h4 = (i - r * (HDIM / 4)) * 4;
            int u = r * AROW32 + 64 + (h4 >> 1);   // u32 index (hidden at u32 col 64)
            split_store4(A_hi + u, A_lo + u, v);
        }
    }

    // per-thread x-projection column params: col xj, row-half rhalf
    const int xj = tid & 127;
    const int rhalf = tid >> 7;
    const float ws0 = Ws[xj * 3], ws1 = Ws[xj * 3 + 1], ws2 = Ws[xj * 3 + 2];
    const float wp0 = Wp[xj * 3], wp1 = Wp[xj * 3 + 1], wp2 = Wp[xj * 3 + 2];
    const float bsj = bs[xj], bpj = bp[xj];
    __syncthreads();

    for (int t = 0; t < T_STEPS; ++t) {
        // ---- stage plan_t ----
        if (tid < BT * 3) {
            int b = tid / 3, j = tid - b * 3;
            plan_s[tid] = plan[(size_t)(bg0 + b) * (T_STEPS * 3) + t * 3 + j];
        }
        __syncthreads();

        // ---- x = state@Ws^T + bs + gate*(plan@Wp^T + bp), split hi/lo ----
        for (int b = rhalf * 32; b < rhalf * 32 + 32; ++b) {
            float v = fmaf(ws0, st_s[b * 3], fmaf(ws1, st_s[b * 3 + 1],
                      fmaf(ws2, st_s[b * 3 + 2], bsj)))
                    + gate_s[b] * fmaf(wp0, plan_s[b * 3], fmaf(wp1, plan_s[b * 3 + 1],
                                  fmaf(wp2, plan_s[b * 3 + 2], bpj)));
            __nv_bfloat16 hh = __float2bfloat16(v);
            Ahi16[b * (AROW32 * 2) + xj] = hh;
            Alo16[b * (AROW32 * 2) + xj] = __float2bfloat16(v - __bfloat162float(hh));
        }
        __syncthreads();

        // =============== main GEMM: [64x512] * [512x1536] ===============
        #pragma unroll
        for (int p = 0; p < 2; ++p) {   // prologue: slabs 0,1
            const uint32_t* s = g_Wf + (size_t)p * SLAB_U32 + tid * 16;
            uint32_t* d = wbuf + p * SLAB_U32 + tid * 16;
            cp16s(d, s); cp16s(d + 4, s + 4); cp16s(d + 8, s + 8); cp16s(d + 12, s + 12);
            cp_commit();
        }

        int it = 0;
        for (int c = 0; c < NCHUNK; ++c) {
            float acc[2][4][4];
            #pragma unroll
            for (int mt = 0; mt < 2; ++mt)
            #pragma unroll
            for (int nt = 0; nt < 4; ++nt) {
                int col = c * 128 + nw * 32 + nt * 8 + 2 * tg;
                float b0v = bias_s[col], b1v = bias_s[col + 1];
                acc[mt][nt][0] = b0v; acc[mt][nt][1] = b1v;
                acc[mt][nt][2] = b0v; acc[mt][nt][3] = b1v;
            }

            for (int sl = 0; sl < 16; ++sl, ++it) {
                cp_wait<1>();
                __syncthreads();          // slab `it` ready; prev compute done
                {
                    int pit = it + 2;     // prefetch 2 ahead (into buffer (it-1)%3)
                    if (pit < MAIN_SLABS) {
                        const uint32_t* s = g_Wf + (size_t)pit * SLAB_U32 + tid * 16;
                        uint32_t* d = wbuf + (pit % 3) * SLAB_U32 + tid * 16;
                        cp16s(d, s);         cp16s(d + 4, s + 4);
                        cp16s(d + 8, s + 8); cp16s(d + 12, s + 12);
                    }
                    cp_commit();
                }
                const uint32_t* buf = wbuf + (it % 3) * SLAB_U32;

                #pragma unroll
                for (int ksl = 0; ksl < 2; ++ksl) {
                    const uint32_t* bb = buf + ksl * 2048;
                    uint2 bh[4], bl[4];
                    #pragma unroll
                    for (int nt = 0; nt < 4; ++nt) {
                        int off = (nw * 4 + nt) * 64 + lane * 2;
                        bh[nt] = *(const uint2*)(bb + off);
                        bl[nt] = *(const uint2*)(bb + 1024 + off);
                    }
                    int kb8 = (sl * 2 + ksl) * 8;
                    #pragma unroll
                    for (int mt = 0; mt < 2; ++mt) {
                        int r0 = (mw * 32 + mt * 16 + gid) * AROW32 + kb8 + tg;
                        int r1 = r0 + 8 * AROW32;
                        uint32_t ah0 = A_hi[r0],     ah1 = A_hi[r1];
                        uint32_t ah2 = A_hi[r0 + 4], ah3 = A_hi[r1 + 4];
                        uint32_t al0 = A_lo[r0],     al1 = A_lo[r1];
                        uint32_t al2 = A_lo[r0 + 4], al3 = A_lo[r1 + 4];
                        #pragma unroll
                        for (int nt = 0; nt < 4; ++nt) {
                            mma16816(acc[mt][nt], ah0, ah1, ah2, ah3, bh[nt].x, bh[nt].y);
                            mma16816(acc[mt][nt], ah0, ah1, ah2, ah3, bl[nt].x, bl[nt].y);
                            mma16816(acc[mt][nt], al0, al1, al2, al3, bh[nt].x, bh[nt].y);
                        }
                    }
                }
            }

            // ---- GRU pointwise: even tg holds (r,z), odd tg holds (s,hn); xor-1 pair ----
            #pragma unroll
            for (int mt = 0; mt < 2; ++mt)
            #pragma unroll
            for (int nt = 0; nt < 4; ++nt) {
                float p0 = __shfl_xor_sync(0xffffffffu, acc[mt][nt][0], 1);
                float p1 = __shfl_xor_sync(0xffffffffu, acc[mt][nt][1], 1);
                float p2 = __shfl_xor_sync(0xffffffffu, acc[mt][nt][2], 1);
                float p3 = __shfl_xor_sync(0xffffffffu, acc[mt][nt][3], 1);
                if ((tg & 1) == 0) {
                    int h = c * 32 + nw * 8 + nt * 2 + (tg >> 1);
                    size_t gr = (size_t)(bg0 + mw * 32 + mt * 16 + gid) * HDIM + h;
                    float rg = sigmoid_f(acc[mt][nt][0]);
                    float zg = sigmoid_f(acc[mt][nt][1]);
                    float ng = tanh_f(p0 + (rg - 1.0f) * p1);   // s + (r-1)*hn
                    float oh = g_hidden[gr];
                    g_hidden[gr] = (1.0f - zg) * ng + zg * oh;
                    float rg2 = sigmoid_f(acc[mt][nt][2]);
                    float zg2 = sigmoid_f(acc[mt][nt][3]);
                    float ng2 = tanh_f(p2 + (rg2 - 1.0f) * p3);
                    size_t gr8 = gr + (size_t)8 * HDIM;
                    float oh8 = g_hidden[gr8];
                    g_hidden[gr8] = (1.0f - zg2) * ng2 + zg2 * oh8;
                }
            }
        }
        __syncthreads();   // all pointwise g_hidden writes done

        // ---- refresh A smem hidden region (hi/lo) from fp32 g_hidden ----
        {
            const float4* gh = (const float4*)(g_hidden + (size_t)bg0 * HDIM);
            for (int i = tid; i < BT * HDIM / 4; i += NTH) {
                float4 v = gh[i];
                int r = i / (HDIM / 4);
                int h4 = (i - r * (HDIM / 4)) * 4;
                int u = r * AROW32 + 64 + (h4 >> 1);
                split_store4(A_hi + u, A_lo + u, v);
            }
        }
        __syncthreads();

        // ======= decode GEMM: d1 = elu(hidden@Wd1^T + bd1), [64x64], K=384 =======
        {
            #pragma unroll
            for (int p = 0; p < 2; ++p) {
                const uint32_t* s = g_Wd1f + p * DSLAB_U32 + tid * 8;
                uint32_t* d = wbuf + p * DSLAB_U32 + tid * 8;
                cp16s(d, s); cp16s(d + 4, s + 4);
                cp_commit();
            }
            float accd[2][2][4];
            #pragma unroll
            for (int mt = 0; mt < 2; ++mt)
            #pragma unroll
            for (int nt = 0; nt < 2; ++nt) {
                int col = nw * 16 + nt * 8 + 2 * tg;
                float b0v = bd1_s[col], b1v = bd1_s[col + 1];
                accd[mt][nt][0] = b0v; accd[mt][nt][1] = b1v;
                accd[mt][nt][2] = b0v; accd[mt][nt][3] = b1v;
            }
            for (int s = 0; s < DEC_SLABS; ++s) {
                cp_wait<1>();
                __syncthreads();
                {
                    int p = s + 2;
                    if (p < DEC_SLABS) {
                        const uint32_t* sp = g_Wd1f + p * DSLAB_U32 + tid * 8;
                        uint32_t* d = wbuf + (p % 3) * DSLAB_U32 + tid * 8;
                        cp16s(d, sp); cp16s(d + 4, sp + 4);
                    }
                    cp_commit();
                }
                const uint32_t* buf = wbuf + (s % 3) * DSLAB_U32;
                #pragma unroll
                for (int ksl = 0; ksl < 2; ++ksl) {
                    const uint32_t* bb = buf + ksl * 1024;
                    uint2 bh[2], bl[2];
                    #pragma unroll
                    for (int nt = 0; nt < 2; ++nt) {
                        int off = (nw * 2 + nt) * 64 + lane * 2;
                        bh[nt] = *(const uint2*)(bb + off);
                        bl[nt] = *(const uint2*)(bb + 512 + off);
                    }
                    int kb8 = 64 + (s * 2 + ksl) * 8;   // hidden region of A
                    #pragma unroll
                    for (int mt = 0; mt < 2; ++mt) {
                        int r0 = (mw * 32 + mt * 16 + gid) * AROW32 + kb8 + tg;
                        int r1 = r0 + 8 * AROW32;
                        uint32_t ah0 = A_hi[r0],     ah1 = A_hi[r1];
                        uint32_t ah2 = A_hi[r0 + 4], ah3 = A_hi[r1 + 4];
                        uint32_t al0 = A_lo[r0],     al1 = A_lo[r1];
                        uint32_t al2 = A_lo[r0 + 4], al3 = A_lo[r1 + 4];
                        #pragma unroll
                        for (int nt = 0; nt < 2; ++nt) {
                            mma16816(accd[mt][nt], ah0, ah1, ah2, ah3, bh[nt].x, bh[nt].y);
                            mma16816(accd[mt][nt], ah0, ah1, ah2, ah3, bl[nt].x, bl[nt].y);
                            mma16816(accd[mt][nt], al0, al1, al2, al3, bh[nt].x, bh[nt].y);
                        }
                    }
                }
            }
            // ELU -> d1s
            #pragma unroll
            for (int mt = 0; mt < 2; ++mt)
            #pragma unroll
            for (int nt = 0; nt < 2; ++nt) {
                int col = nw * 16 + nt * 8 + 2 * tg;
                int row = mw * 32 + mt * 16 + gid;
                d1s[row * D1PAD + col]           = elu_f(accd[mt][nt][0]);
                d1s[row * D1PAD + col + 1]       = elu_f(accd[mt][nt][1]);
                d1s[(row + 8) * D1PAD + col]     = elu_f(accd[mt][nt][2]);
                d1s[(row + 8) * D1PAD + col + 1] = elu_f(accd[mt][nt][3]);
            }
        }
        __syncthreads();

        // ---- decode layer 2 + state update + output ----
        if (tid < BT * 3) {
            int b = tid / 3, j = tid - b * 3;
            const float* w = wd2_s + j * 64;
            const float* d = d1s + b * D1PAD;
            float sum = bd2_s[j];
            #pragma unroll
            for (int k = 0; k < 64; ++k)
                sum = fmaf(d[k], w[k], sum);
            float ns = st_s[tid] + sum;
            st_s[tid] = ns;
            out[(size_t)(bg0 + b) * (T_STEPS * 3) + t * 3 + j] = ns;
        }
        __syncthreads();
    }
}

// ----------------------------------------------------------------------------
extern "C" void kernel_launch(void* const* d_in, const int* in_sizes, int n_in,
                              void* d_out, int out_size)
{
    (void)in_sizes; (void)n_in; (void)out_size;
    const float* init_hidden = (const float*)d_in[0];
    const float* plan        = (const float*)d_in[1];
    const float* gate        = (const float*)d_in[2];
    const float* init_state  = (const float*)d_in[3];
    const float* Wp   = (const float*)d_in[4];
    const float* bp   = (const float*)d_in[5];
    const float* Ws   = (const float*)d_in[6];
    const float* bs   = (const float*)d_in[7];
    const float* W_ih = (const float*)d_in[8];
    const float* b_ih = (const float*)d_in[9];
    const float* W_hh = (const float*)d_in[10];
    const float* b_hh = (const float*)d_in[11];
    const float* Wd1  = (const float*)d_in[12];
    const float* bd1  = (const float*)d_in[13];
    const float* Wd2  = (const float*)d_in[14];
    const float* bd2  = (const float*)d_in[15];
    float* out = (float*)d_out;

    pack_kernel<<<(KTOT * NCOLS + 255) / 256, 256>>>(W_ih, W_hh, b_ih, b_hh, Wd1);

    const int smem_bytes = (2 * A_U32 + 3 * SLAB_U32 + BT * D1PAD + NCOLS
                            + D1 + 192 + 4 + BT * 3 + BT * 3 + BT) * 4;
    cudaFuncSetAttribute(decoder_kernel,
                         cudaFuncAttributeMaxDynamicSharedMemorySize, smem_bytes);
    decoder_kernel<<<B_TOTAL / BT, NTH, smem_bytes>>>(
        init_hidden, plan, gate, init_state,
        Wp, bp, Ws, bs, Wd2, bd2, bd1, out);
}

// round 7
// speedup vs baseline: 2.0237x; 1.2569x over previous
#include <cuda_runtime.h>
#include <cuda_bf16.h>
#include <cstdint>
#include <cstddef>

// ---------------- problem constants ----------------
#define B_TOTAL 32768
#define T_STEPS 30
#define HDIM    384
#define BT      64          // batch rows per CTA
#define NTH     256         // 8 warps
#define KTOT    512         // [x(128) | hidden(384)]
#define NCOLS   1536        // 384 h * 4 gates (r,z,s,hn), gate-interleaved
#define NCHUNK  12          // 128 cols per chunk
#define SLAB_U32 4096       // 16KB: one slab = 2 ksteps(32 k) x 128 cols, hi+lo fused
#define MAIN_SLABS 192      // 12 chunks * 16 slabs
#define DEC_SLABS  12       // decode K=384 -> 12 slabs of 2 ksteps
#define DSLAB_U32  2048     // 8KB per decode slab
#define D1      64
#define D1PAD   65
#define A_U32   32768       // 32 ksteps * 1024 u32 (frag-ordered, hi+lo)

// ---------------- device scratch (no allocations allowed) ----------------
__device__ uint32_t g_Wf[(size_t)MAIN_SLABS * SLAB_U32];   // 3 MB main-W frags
__device__ uint32_t g_Wd1f[DEC_SLABS * DSLAB_U32];         // 96 KB Wd1 frags
__device__ float    g_bias[NCOLS];
__device__ float    g_hidden[(size_t)B_TOTAL * HDIM];      // fp32 recurrent state

// ---------------- helpers ----------------
__device__ __forceinline__ void cp16s(void* dst, const void* src) {
    unsigned d = (unsigned)__cvta_generic_to_shared(dst);
    asm volatile("cp.async.ca.shared.global [%0], [%1], 16;\n" :: "r"(d), "l"(src));
}
__device__ __forceinline__ void cp_commit() { asm volatile("cp.async.commit_group;\n"); }
template<int N> __device__ __forceinline__ void cp_wait() {
    asm volatile("cp.async.wait_group %0;\n" :: "n"(N));
}
__device__ __forceinline__ float sigmoid_f(float x) { return 1.0f / (1.0f + __expf(-x)); }
__device__ __forceinline__ float tanh_f(float x) {
    float e2 = __expf(2.0f * x);
    return 1.0f - 2.0f / (e2 + 1.0f);
}
__device__ __forceinline__ float elu_f(float x) {
    return x > 0.0f ? x : (__expf(x) - 1.0f);
}
__device__ __forceinline__ void mma16816(float* c,
    uint32_t a0, uint32_t a1, uint32_t a2, uint32_t a3, uint32_t b0, uint32_t b1)
{
    asm volatile(
        "mma.sync.aligned.m16n8k16.row.col.f32.bf16.bf16.f32 "
        "{%0,%1,%2,%3}, {%4,%5,%6,%7}, {%8,%9}, {%0,%1,%2,%3};\n"
        : "+f"(c[0]), "+f"(c[1]), "+f"(c[2]), "+f"(c[3])
        : "r"(a0), "r"(a1), "r"(a2), "r"(a3), "r"(b0), "r"(b1));
}

// Write element pair (row, k even, k+1) into frag-ordered A smem (hi + lo).
// A layout (u32): kstep*1024 + mt*256 + [hi:0 | lo:128] + lane*4 + reg
// reg = hi8 + 2*k8 (a0..a3 mapping of m16n8k16), lane = gid*4 + tg2.
__device__ __forceinline__ void a_write_pair(uint32_t* A, int row, int k,
                                             float v0, float v1)
{
    int kstep = k >> 4, kk = k & 15;
    int mt = row >> 4, r16 = row & 15;
    int gid = r16 & 7, hi8 = r16 >> 3;
    int tg2 = (kk & 7) >> 1, k8 = kk >> 3;
    int reg = hi8 + 2 * k8;
    int lane = gid * 4 + tg2;
    uint32_t uidx = kstep * 1024 + mt * 256 + lane * 4 + reg;
    __nv_bfloat16 h0 = __float2bfloat16(v0);
    __nv_bfloat16 h1 = __float2bfloat16(v1);
    unsigned hw = (unsigned)__bfloat16_as_ushort(h0)
                | ((unsigned)__bfloat16_as_ushort(h1) << 16);
    unsigned lw = (unsigned)__bfloat16_as_ushort(__float2bfloat16(v0 - __bfloat162float(h0)))
                | ((unsigned)__bfloat16_as_ushort(__float2bfloat16(v1 - __bfloat162float(h1))) << 16);
    A[uidx]       = hw;
    A[uidx + 128] = lw;
}

// ----------------------------------------------------------------------------
// Pack: W = [W_ih | W_hh] -> bf16 hi/lo, fused-fragment order.
// B u32 layout per kstep block (2048 u32): ntg*128 + lane*4 + {0,1:hi | 2,3:lo};
// bf16 element at u32*2 + half.  Col q: g=q&3 (0=r,1=z,2=s(inn+hn),3=hn zero-pad
// k<128), i=q>>2, h=chunk*32+i; ntg=q>>3, n=q&7, lane=n*4+tg2; kk=k&15,
// tg2=(kk&7)>>1, reg=kk>>3, half=kk&1.
// ----------------------------------------------------------------------------
__global__ void pack_kernel(const float* __restrict__ W_ih,
                            const float* __restrict__ W_hh,
                            const float* __restrict__ b_ih,
                            const float* __restrict__ b_hh,
                            const float* __restrict__ Wd1)
{
    int idx = blockIdx.x * blockDim.x + threadIdx.x;
    __nv_bfloat16* Wf16   = (__nv_bfloat16*)g_Wf;
    __nv_bfloat16* Wd1f16 = (__nv_bfloat16*)g_Wd1f;

    if (idx < KTOT * NCOLS) {
        int k = idx / NCOLS;
        int col = idx - k * NCOLS;
        int chunk = col >> 7, q = col & 127;
        int i = q >> 2, g = q & 3, h = chunk * 32 + i;
        float v;
        if (g < 3) {
            int row = g * HDIM + h;
            v = (k < 128) ? W_ih[row * 128 + k] : W_hh[row * HDIM + (k - 128)];
        } else {
            v = (k < 128) ? 0.0f : W_hh[(2 * HDIM + h) * HDIM + (k - 128)];
        }
        __nv_bfloat16 hi = __float2bfloat16(v);
        __nv_bfloat16 lo = __float2bfloat16(v - __bfloat162float(hi));
        int kstep = k >> 4, kk = k & 15;
        int reg = kk >> 3, tg2 = (kk & 7) >> 1, half = kk & 1;
        int ntg = q >> 3, n = q & 7;
        int lane = n * 4 + tg2;
        size_t base = (size_t)(chunk * 32 + kstep) * 2048;
        size_t uhi = base + ntg * 128 + lane * 4 + reg;
        Wf16[uhi * 2 + half]       = hi;
        Wf16[(uhi + 2) * 2 + half] = lo;
    }
    if (idx < HDIM * D1) {     // Wd1 [64][384]; per kstep block = 1024 u32
        int k = idx >> 6, j = idx & 63;
        float v = Wd1[j * HDIM + k];
        __nv_bfloat16 hi = __float2bfloat16(v);
        __nv_bfloat16 lo = __float2bfloat16(v - __bfloat162float(hi));
        int kstep = k >> 4, kk = k & 15;
        int reg = kk >> 3, tg2 = (kk & 7) >> 1, half = kk & 1;
        int ntg = j >> 3, n = j & 7;
        int lane = n * 4 + tg2;
        size_t uhi = (size_t)kstep * 1024 + ntg * 128 + lane * 4 + reg;
        Wd1f16[uhi * 2 + half]       = hi;
        Wd1f16[(uhi + 2) * 2 + half] = lo;
    }
    if (idx < NCOLS) {
        int c = idx >> 7, q = idx & 127, i = q >> 2, g = q & 3;
        int h = c * 32 + i;
        float bv;
        if (g == 3) bv = b_hh[2 * HDIM + h];
        else        bv = b_ih[g * HDIM + h] + b_hh[g * HDIM + h];
        g_bias[idx] = bv;
    }
}

// ----------------------------------------------------------------------------
// Persistent per-tile decoder: 64 batch rows, split-bf16 tensor-core GEMMs.
// Warps: mw = warp&1 (2 mtiles of 16 rows), nw = warp>>1 (4 ntiles of 8 cols).
// ----------------------------------------------------------------------------
__global__ void __launch_bounds__(NTH, 1)
decoder_kernel(const float* __restrict__ init_hidden,
               const float* __restrict__ plan,
               const float* __restrict__ gate,
               const float* __restrict__ init_state,
               const float* __restrict__ Wp, const float* __restrict__ bp,
               const float* __restrict__ Ws, const float* __restrict__ bs,
               const float* __restrict__ Wd2, const float* __restrict__ bd2,
               const float* __restrict__ bd1,
               float* __restrict__ out)
{
    extern __shared__ uint32_t sm32[];
    uint32_t* A_f  = sm32;                         // 32768 u32 (128KB)
    uint32_t* wbuf = A_f + A_U32;                  // 4*4096 = 16384 u32 (64KB)
    float* bias_s = (float*)(wbuf + 4 * SLAB_U32); // 1536
    float* xcoef  = bias_s + NCOLS;                // 128*8 = 1024
    float* bd1_s  = xcoef + 1024;                  // 64
    float* wd2_s  = bd1_s + D1;                    // 192
    float* bd2_s  = wd2_s + 192;                   // 4
    float* plan_s = bd2_s + 4;                     // 192
    float* st_s   = plan_s + BT * 3;               // 192
    float* gate_s = st_s + BT * 3;                 // 64
    float* d1s    = (float*)(wbuf + 3 * DSLAB_U32);// alias: 4160 floats in wbuf

    const int tid  = threadIdx.x;
    const int lane = tid & 31;
    const int warp = tid >> 5;
    const int gid  = lane >> 2;      // 0..7
    const int tg   = lane & 3;       // 0..3
    const int mw   = warp & 1;       // 32-row half
    const int nw   = warp >> 1;      // 32-col quarter of 128-chunk
    const int bg0  = blockIdx.x * BT;

    // ---- stage constants ----
    for (int i = tid; i < NCOLS; i += NTH) bias_s[i] = g_bias[i];
    if (tid < 128) {
        xcoef[tid * 8 + 0] = Ws[tid * 3 + 0];
        xcoef[tid * 8 + 1] = Ws[tid * 3 + 1];
        xcoef[tid * 8 + 2] = Ws[tid * 3 + 2];
        xcoef[tid * 8 + 3] = bs[tid];
        xcoef[tid * 8 + 4] = Wp[tid * 3 + 0];
        xcoef[tid * 8 + 5] = Wp[tid * 3 + 1];
        xcoef[tid * 8 + 6] = Wp[tid * 3 + 2];
        xcoef[tid * 8 + 7] = bp[tid];
    }
    if (tid < D1)  bd1_s[tid] = bd1[tid];
    if (tid < 192) wd2_s[tid] = Wd2[tid];
    if (tid < 3)   bd2_s[tid] = bd2[tid];
    if (tid < BT * 3) st_s[tid] = init_state[bg0 * 3 + tid];
    if (tid < BT)     gate_s[tid] = gate[bg0 + tid];

    // ---- init hidden: fp32 -> g_hidden and frag hi/lo -> A smem ----
    {
        const float4* src = (const float4*)(init_hidden + (size_t)bg0 * HDIM);
        float4* gh = (float4*)(g_hidden + (size_t)bg0 * HDIM);
        for (int i = tid; i < BT * HDIM / 4; i += NTH) {
            float4 v = src[i];
            gh[i] = v;
            int r = i / (HDIM / 4);
            int h4 = (i - r * (HDIM / 4)) * 4;
            a_write_pair(A_f, r, 128 + h4,     v.x, v.y);
            a_write_pair(A_f, r, 128 + h4 + 2, v.z, v.w);
        }
    }
    __syncthreads();

    // x-producer mapping: thread -> (row b, 32-col group)
    const int xb  = tid & 63;
    const int xcg = (tid >> 6) * 32;

    for (int t = 0; t < T_STEPS; ++t) {
        // ---- stage plan_t ----
        if (tid < BT * 3) {
            int b = tid / 3, j = tid - b * 3;
            plan_s[tid] = plan[(size_t)(bg0 + b) * (T_STEPS * 3) + t * 3 + j];
        }
        __syncthreads();

        // ---- x = state@Ws^T + bs + gate*(plan@Wp^T + bp), frag hi/lo ----
        {
            float s0 = st_s[xb * 3], s1 = st_s[xb * 3 + 1], s2 = st_s[xb * 3 + 2];
            float p0 = plan_s[xb * 3], p1 = plan_s[xb * 3 + 1], p2 = plan_s[xb * 3 + 2];
            float gt = gate_s[xb];
            #pragma unroll 4
            for (int jj = 0; jj < 32; jj += 2) {
                const float* c0 = xcoef + (xcg + jj) * 8;
                const float* c1 = c0 + 8;
                float v0 = fmaf(c0[0], s0, fmaf(c0[1], s1, fmaf(c0[2], s2, c0[3])))
                         + gt * fmaf(c0[4], p0, fmaf(c0[5], p1, fmaf(c0[6], p2, c0[7])));
                float v1 = fmaf(c1[0], s0, fmaf(c1[1], s1, fmaf(c1[2], s2, c1[3])))
                         + gt * fmaf(c1[4], p0, fmaf(c1[5], p1, fmaf(c1[6], p2, c1[7])));
                a_write_pair(A_f, xb, xcg + jj, v0, v1);
            }
        }
        __syncthreads();

        // =============== main GEMM: [64x512] * [512x1536] ===============
        #pragma unroll
        for (int p = 0; p < 3; ++p) {   // prologue: slabs 0,1,2
            const uint32_t* s = g_Wf + (size_t)p * SLAB_U32 + tid * 16;
            uint32_t* d = wbuf + p * SLAB_U32 + tid * 16;
            cp16s(d, s); cp16s(d + 4, s + 4); cp16s(d + 8, s + 8); cp16s(d + 12, s + 12);
            cp_commit();
        }

        int it = 0;
        for (int c = 0; c < NCHUNK; ++c) {
            float acc[2][4][4];
            #pragma unroll
            for (int mt = 0; mt < 2; ++mt)
            #pragma unroll
            for (int nt = 0; nt < 4; ++nt) {
                int col = c * 128 + nw * 32 + nt * 8 + 2 * tg;
                float b0v = bias_s[col], b1v = bias_s[col + 1];
                acc[mt][nt][0] = b0v; acc[mt][nt][1] = b1v;
                acc[mt][nt][2] = b0v; acc[mt][nt][3] = b1v;
            }
            // prefetch oldh for this chunk's epilogue (hides ~L2 latency)
            float oldv[2][4][2];
            if ((tg & 1) == 0) {
                #pragma unroll
                for (int mt = 0; mt < 2; ++mt)
                #pragma unroll
                for (int nt = 0; nt < 4; ++nt) {
                    int h = c * 32 + nw * 8 + nt * 2 + (tg >> 1);
                    size_t gr = (size_t)(bg0 + mw * 32 + mt * 16 + gid) * HDIM + h;
                    oldv[mt][nt][0] = g_hidden[gr];
                    oldv[mt][nt][1] = g_hidden[gr + (size_t)8 * HDIM];
                }
            }

            for (int sl = 0; sl < 16; ++sl, ++it) {
                cp_wait<2>();
                __syncthreads();          // slab `it` visible; reads of it-1 done
                {
                    int pit = it + 3;
                    if (pit < MAIN_SLABS) {
                        const uint32_t* s = g_Wf + (size_t)pit * SLAB_U32 + tid * 16;
                        uint32_t* d = wbuf + (pit & 3) * SLAB_U32 + tid * 16;
                        cp16s(d, s);         cp16s(d + 4, s + 4);
                        cp16s(d + 8, s + 8); cp16s(d + 12, s + 12);
                    }
                    cp_commit();
                }
                const uint32_t* buf = wbuf + (it & 3) * SLAB_U32;

                #pragma unroll
                for (int ksl = 0; ksl < 2; ++ksl) {
                    const uint32_t* bb = buf + ksl * 2048;
                    uint4 b4[4];
                    #pragma unroll
                    for (int nt = 0; nt < 4; ++nt)
                        b4[nt] = *(const uint4*)(bb + (nw * 4 + nt) * 128 + lane * 4);
                    int kstep = sl * 2 + ksl;
                    uint4 ah[2], al[2];
                    #pragma unroll
                    for (int mt = 0; mt < 2; ++mt) {
                        const uint32_t* ab = A_f + kstep * 1024 + (mw * 2 + mt) * 256 + lane * 4;
                        ah[mt] = *(const uint4*)ab;
                        al[mt] = *(const uint4*)(ab + 128);
                    }
                    // term-major: hh, hl, lh — no back-to-back RAW on any acc
                    #pragma unroll
                    for (int mt = 0; mt < 2; ++mt)
                    #pragma unroll
                    for (int nt = 0; nt < 4; ++nt)
                        mma16816(acc[mt][nt], ah[mt].x, ah[mt].y, ah[mt].z, ah[mt].w,
                                 b4[nt].x, b4[nt].y);
                    #pragma unroll
                    for (int mt = 0; mt < 2; ++mt)
                    #pragma unroll
                    for (int nt = 0; nt < 4; ++nt)
                        mma16816(acc[mt][nt], ah[mt].x, ah[mt].y, ah[mt].z, ah[mt].w,
                                 b4[nt].z, b4[nt].w);
                    #pragma unroll
                    for (int mt = 0; mt < 2; ++mt)
                    #pragma unroll
                    for (int nt = 0; nt < 4; ++nt)
                        mma16816(acc[mt][nt], al[mt].x, al[mt].y, al[mt].z, al[mt].w,
                                 b4[nt].x, b4[nt].y);
                }
            }

            // ---- GRU pointwise: even tg has (r,z), odd tg has (s,hn); xor-1 pair ----
            #pragma unroll
            for (int mt = 0; mt < 2; ++mt)
            #pragma unroll
            for (int nt = 0; nt < 4; ++nt) {
                float p0 = __shfl_xor_sync(0xffffffffu, acc[mt][nt][0], 1);
                float p1 = __shfl_xor_sync(0xffffffffu, acc[mt][nt][1], 1);
                float p2 = __shfl_xor_sync(0xffffffffu, acc[mt][nt][2], 1);
                float p3 = __shfl_xor_sync(0xffffffffu, acc[mt][nt][3], 1);
                if ((tg & 1) == 0) {
                    int h = c * 32 + nw * 8 + nt * 2 + (tg >> 1);
                    size_t gr = (size_t)(bg0 + mw * 32 + mt * 16 + gid) * HDIM + h;
                    float rg = sigmoid_f(acc[mt][nt][0]);
                    float zg = sigmoid_f(acc[mt][nt][1]);
                    float ng = tanh_f(p0 + (rg - 1.0f) * p1);   // s + (r-1)*hn
                    g_hidden[gr] = (1.0f - zg) * ng + zg * oldv[mt][nt][0];
                    float rg2 = sigmoid_f(acc[mt][nt][2]);
                    float zg2 = sigmoid_f(acc[mt][nt][3]);
                    float ng2 = tanh_f(p2 + (rg2 - 1.0f) * p3);
                    g_hidden[gr + (size_t)8 * HDIM] =
                        (1.0f - zg2) * ng2 + zg2 * oldv[mt][nt][1];
                }
            }
        }
        __syncthreads();   // all pointwise g_hidden writes done

        // ---- refresh A smem hidden frags (hi/lo) from fp32 g_hidden ----
        {
            const float4* gh = (const float4*)(g_hidden + (size_t)bg0 * HDIM);
            for (int i = tid; i < BT * HDIM / 4; i += NTH) {
                float4 v = gh[i];
                int r = i / (HDIM / 4);
                int h4 = (i - r * (HDIM / 4)) * 4;
                a_write_pair(A_f, r, 128 + h4,     v.x, v.y);
                a_write_pair(A_f, r, 128 + h4 + 2, v.z, v.w);
            }
        }
        __syncthreads();

        // ======= decode GEMM: d1 = elu(hidden@Wd1^T + bd1), [64x64], K=384 =======
        {
            #pragma unroll
            for (int p = 0; p < 2; ++p) {
                const uint32_t* s = g_Wd1f + p * DSLAB_U32 + tid * 8;
                uint32_t* d = wbuf + p * DSLAB_U32 + tid * 8;
                cp16s(d, s); cp16s(d + 4, s + 4);
                cp_commit();
            }
            float accd[2][2][4];
            #pragma unroll
            for (int mt = 0; mt < 2; ++mt)
            #pragma unroll
            for (int nt = 0; nt < 2; ++nt) {
                int col = nw * 16 + nt * 8 + 2 * tg;
                float b0v = bd1_s[col], b1v = bd1_s[col + 1];
                accd[mt][nt][0] = b0v; accd[mt][nt][1] = b1v;
                accd[mt][nt][2] = b0v; accd[mt][nt][3] = b1v;
            }
            for (int s = 0; s < DEC_SLABS; ++s) {
                cp_wait<1>();
                __syncthreads();
                {
                    int p = s + 2;
                    if (p < DEC_SLABS) {
                        const uint32_t* sp = g_Wd1f + p * DSLAB_U32 + tid * 8;
                        uint32_t* d = wbuf + (p % 3) * DSLAB_U32 + tid * 8;
                        cp16s(d, sp); cp16s(d + 4, sp + 4);
                    }
                    cp_commit();
                }
                const uint32_t* buf = wbuf + (s % 3) * DSLAB_U32;
                #pragma unroll
                for (int ksl = 0; ksl < 2; ++ksl) {
                    const uint32_t* bb = buf + ksl * 1024;
                    uint4 b4[2];
                    #pragma unroll
                    for (int nt = 0; nt < 2; ++nt)
                        b4[nt] = *(const uint4*)(bb + (nw * 2 + nt) * 128 + lane * 4);
                    int kstep = 8 + s * 2 + ksl;   // hidden region of A
                    uint4 ah[2], al[2];
                    #pragma unroll
                    for (int mt = 0; mt < 2; ++mt) {
                        const uint32_t* ab = A_f + kstep * 1024 + (mw * 2 + mt) * 256 + lane * 4;
                        ah[mt] = *(const uint4*)ab;
                        al[mt] = *(const uint4*)(ab + 128);
                    }
                    #pragma unroll
                    for (int mt = 0; mt < 2; ++mt)
                    #pragma unroll
                    for (int nt = 0; nt < 2; ++nt)
                        mma16816(accd[mt][nt], ah[mt].x, ah[mt].y, ah[mt].z, ah[mt].w,
                                 b4[nt].x, b4[nt].y);
                    #pragma unroll
                    for (int mt = 0; mt < 2; ++mt)
                    #pragma unroll
                    for (int nt = 0; nt < 2; ++nt)
                        mma16816(accd[mt][nt], ah[mt].x, ah[mt].y, ah[mt].z, ah[mt].w,
                                 b4[nt].z, b4[nt].w);
                    #pragma unroll
                    for (int mt = 0; mt < 2; ++mt)
                    #pragma unroll
                    for (int nt = 0; nt < 2; ++nt)
                        mma16816(accd[mt][nt], al[mt].x, al[mt].y, al[mt].z, al[mt].w,
                                 b4[nt].x, b4[nt].y);
                }
            }
            __syncthreads();   // decode buffers dead before d1s alias is written
            // ELU -> d1s
            #pragma unroll
            for (int mt = 0; mt < 2; ++mt)
            #pragma unroll
            for (int nt = 0; nt < 2; ++nt) {
                int col = nw * 16 + nt * 8 + 2 * tg;
                int row = mw * 32 + mt * 16 + gid;
                d1s[row * D1PAD + col]           = elu_f(accd[mt][nt][0]);
                d1s[row * D1PAD + col + 1]       = elu_f(accd[mt][nt][1]);
                d1s[(row + 8) * D1PAD + col]     = elu_f(accd[mt][nt][2]);
                d1s[(row + 8) * D1PAD + col + 1] = elu_f(accd[mt][nt][3]);
            }
        }
        __syncthreads();

        // ---- decode layer 2 + state update + output ----
        if (tid < BT * 3) {
            int b = tid / 3, j = tid - b * 3;
            const float* w = wd2_s + j * 64;
            const float* d = d1s + b * D1PAD;
            float sum = bd2_s[j];
            #pragma unroll
            for (int k = 0; k < 64; ++k)
                sum = fmaf(d[k], w[k], sum);
            float ns = st_s[tid] + sum;
            st_s[tid] = ns;
            out[(size_t)(bg0 + b) * (T_STEPS * 3) + t * 3 + j] = ns;
        }
        __syncthreads();
    }
}

// ----------------------------------------------------------------------------
extern "C" void kernel_launch(void* const* d_in, const int* in_sizes, int n_in,
                              void* d_out, int out_size)
{
    (void)in_sizes; (void)n_in; (void)out_size;
    const float* init_hidden = (const float*)d_in[0];
    const float* plan        = (const float*)d_in[1];
    const float* gate        = (const float*)d_in[2];
    const float* init_state  = (const float*)d_in[3];
    const float* Wp   = (const float*)d_in[4];
    const float* bp   = (const float*)d_in[5];
    const float* Ws   = (const float*)d_in[6];
    const float* bs   = (const float*)d_in[7];
    const float* W_ih = (const float*)d_in[8];
    const float* b_ih = (const float*)d_in[9];
    const float* W_hh = (const float*)d_in[10];
    const float* b_hh = (const float*)d_in[11];
    const float* Wd1  = (const float*)d_in[12];
    const float* bd1  = (const float*)d_in[13];
    const float* Wd2  = (const float*)d_in[14];
    const float* bd2  = (const float*)d_in[15];
    float* out = (float*)d_out;

    pack_kernel<<<(KTOT * NCOLS + 255) / 256, 256>>>(W_ih, W_hh, b_ih, b_hh, Wd1);

    const int smem_bytes = (A_U32 + 4 * SLAB_U32 + NCOLS + 1024
                            + D1 + 192 + 4 + BT * 3 + BT * 3 + BT) * 4;
    cudaFuncSetAttribute(decoder_kernel,
                         cudaFuncAttributeMaxDynamicSharedMemorySize, smem_bytes);
    decoder_kernel<<<B_TOTAL / BT, NTH, smem_bytes>>>(
        init_hidden, plan, gate, init_state,
        Wp, bp, Ws, bs, Wd2, bd2, bd1, out);
}

// round 8
// speedup vs baseline: 2.0280x; 1.0022x over previous
#include <cuda_runtime.h>
#include <cuda_bf16.h>
#include <cstdint>
#include <cstddef>

// ---------------- problem constants ----------------
#define B_TOTAL 32768
#define T_STEPS 30
#define HDIM    384
#define BT      64          // batch rows per CTA
#define NTH     256         // 8 warps
#define KTOT    512         // [x(128) | hidden(384)]
#define NCOLS   1536        // 384 h * 4 gates (r,z,s,hn), gate-interleaved
#define NCHUNK  12          // 128 cols per chunk
#define SLAB_U32 4096       // 16KB: one slab = 2 ksteps(32 k) x 128 cols, hi+lo fused
#define MAIN_SLABS 192      // 12 chunks * 16 slabs
#define DEC_SLABS  12       // decode K=384 -> 12 slabs of 2 ksteps
#define DSLAB_U32  2048     // 8KB per decode slab
#define D1      64
#define D1PAD   65
#define A_U32   32768       // 32 ksteps * 1024 u32 (frag-ordered, hi+lo)

// ---------------- device scratch (no allocations allowed) ----------------
__device__ uint32_t g_Wf[(size_t)MAIN_SLABS * SLAB_U32];   // 3 MB main-W frags
__device__ uint32_t g_Wd1f[DEC_SLABS * DSLAB_U32];         // 96 KB Wd1 frags
__device__ float    g_bias[NCOLS];
__device__ float    g_hidden[(size_t)B_TOTAL * HDIM];      // fp32 recurrent state

// ---------------- helpers ----------------
__device__ __forceinline__ void cp16s(void* dst, const void* src) {
    unsigned d = (unsigned)__cvta_generic_to_shared(dst);
    asm volatile("cp.async.ca.shared.global [%0], [%1], 16;\n" :: "r"(d), "l"(src));
}
__device__ __forceinline__ void cp_commit() { asm volatile("cp.async.commit_group;\n"); }
template<int N> __device__ __forceinline__ void cp_wait() {
    asm volatile("cp.async.wait_group %0;\n" :: "n"(N));
}
__device__ __forceinline__ float sigmoid_f(float x) { return 1.0f / (1.0f + __expf(-x)); }
__device__ __forceinline__ float tanh_f(float x) {
    float e2 = __expf(2.0f * x);
    return 1.0f - 2.0f / (e2 + 1.0f);
}
__device__ __forceinline__ float elu_f(float x) {
    return x > 0.0f ? x : (__expf(x) - 1.0f);
}
__device__ __forceinline__ void mma16816(float* c,
    uint32_t a0, uint32_t a1, uint32_t a2, uint32_t a3, uint32_t b0, uint32_t b1)
{
    asm volatile(
        "mma.sync.aligned.m16n8k16.row.col.f32.bf16.bf16.f32 "
        "{%0,%1,%2,%3}, {%4,%5,%6,%7}, {%8,%9}, {%0,%1,%2,%3};\n"
        : "+f"(c[0]), "+f"(c[1]), "+f"(c[2]), "+f"(c[3])
        : "r"(a0), "r"(a1), "r"(a2), "r"(a3), "r"(b0), "r"(b1));
}

// Write element pair (row, k even, k+1) into frag-ordered A smem (hi + lo).
// A layout (u32): kstep*1024 + mt*256 + [hi:0 | lo:128] + lane*4 + reg
// reg = hi8 + 2*k8 (a0..a3 mapping of m16n8k16), lane = gid*4 + tg2.
__device__ __forceinline__ void a_write_pair(uint32_t* A, int row, int k,
                                             float v0, float v1)
{
    int kstep = k >> 4, kk = k & 15;
    int mt = row >> 4, r16 = row & 15;
    int gid = r16 & 7, hi8 = r16 >> 3;
    int tg2 = (kk & 7) >> 1, k8 = kk >> 3;
    int reg = hi8 + 2 * k8;
    int lane = gid * 4 + tg2;
    uint32_t uidx = kstep * 1024 + mt * 256 + lane * 4 + reg;
    __nv_bfloat16 h0 = __float2bfloat16(v0);
    __nv_bfloat16 h1 = __float2bfloat16(v1);
    unsigned hw = (unsigned)__bfloat16_as_ushort(h0)
                | ((unsigned)__bfloat16_as_ushort(h1) << 16);
    unsigned lw = (unsigned)__bfloat16_as_ushort(__float2bfloat16(v0 - __bfloat162float(h0)))
                | ((unsigned)__bfloat16_as_ushort(__float2bfloat16(v1 - __bfloat162float(h1))) << 16);
    A[uidx]       = hw;
    A[uidx + 128] = lw;
}

// ----------------------------------------------------------------------------
// Pack: W = [W_ih | W_hh] -> bf16 hi/lo, fused-fragment order.
// B u32 layout per kstep block (2048 u32): ntg*128 + lane*4 + {0,1:hi | 2,3:lo};
// bf16 element at u32*2 + half.  Col q: g=q&3 (0=r,1=z,2=s(inn+hn),3=hn zero-pad
// k<128), i=q>>2, h=chunk*32+i; ntg=q>>3, n=q&7, lane=n*4+tg2; kk=k&15,
// tg2=(kk&7)>>1, reg=kk>>3, half=kk&1.
// ----------------------------------------------------------------------------
__global__ void pack_kernel(const float* __restrict__ W_ih,
                            const float* __restrict__ W_hh,
                            const float* __restrict__ b_ih,
                            const float* __restrict__ b_hh,
                            const float* __restrict__ Wd1)
{
    int idx = blockIdx.x * blockDim.x + threadIdx.x;
    __nv_bfloat16* Wf16   = (__nv_bfloat16*)g_Wf;
    __nv_bfloat16* Wd1f16 = (__nv_bfloat16*)g_Wd1f;

    if (idx < KTOT * NCOLS) {
        int k = idx / NCOLS;
        int col = idx - k * NCOLS;
        int chunk = col >> 7, q = col & 127;
        int i = q >> 2, g = q & 3, h = chunk * 32 + i;
        float v;
        if (g < 3) {
            int row = g * HDIM + h;
            v = (k < 128) ? W_ih[row * 128 + k] : W_hh[row * HDIM + (k - 128)];
        } else {
            v = (k < 128) ? 0.0f : W_hh[(2 * HDIM + h) * HDIM + (k - 128)];
        }
        __nv_bfloat16 hi = __float2bfloat16(v);
        __nv_bfloat16 lo = __float2bfloat16(v - __bfloat162float(hi));
        int kstep = k >> 4, kk = k & 15;
        int reg = kk >> 3, tg2 = (kk & 7) >> 1, half = kk & 1;
        int ntg = q >> 3, n = q & 7;
        int lane = n * 4 + tg2;
        size_t base = (size_t)(chunk * 32 + kstep) * 2048;
        size_t uhi = base + ntg * 128 + lane * 4 + reg;
        Wf16[uhi * 2 + half]       = hi;
        Wf16[(uhi + 2) * 2 + half] = lo;
    }
    if (idx < HDIM * D1) {     // Wd1 [64][384]; per kstep block = 1024 u32
        int k = idx >> 6, j = idx & 63;
        float v = Wd1[j * HDIM + k];
        __nv_bfloat16 hi = __float2bfloat16(v);
        __nv_bfloat16 lo = __float2bfloat16(v - __bfloat162float(hi));
        int kstep = k >> 4, kk = k & 15;
        int reg = kk >> 3, tg2 = (kk & 7) >> 1, half = kk & 1;
        int ntg = j >> 3, n = j & 7;
        int lane = n * 4 + tg2;
        size_t uhi = (size_t)kstep * 1024 + ntg * 128 + lane * 4 + reg;
        Wd1f16[uhi * 2 + half]       = hi;
        Wd1f16[(uhi + 2) * 2 + half] = lo;
    }
    if (idx < NCOLS) {
        int c = idx >> 7, q = idx & 127, i = q >> 2, g = q & 3;
        int h = c * 32 + i;
        float bv;
        if (g == 3) bv = b_hh[2 * HDIM + h];
        else        bv = b_ih[g * HDIM + h] + b_hh[g * HDIM + h];
        g_bias[idx] = bv;
    }
}

// ----------------------------------------------------------------------------
// Persistent per-tile decoder: 64 batch rows, split-bf16 tensor-core GEMMs.
// Warps: mw = warp&1 (2 mtiles of 16 rows), nw = warp>>1 (4 ntiles of 8 cols).
// ----------------------------------------------------------------------------
__global__ void __launch_bounds__(NTH, 1)
decoder_kernel(const float* __restrict__ init_hidden,
               const float* __restrict__ plan,
               const float* __restrict__ gate,
               const float* __restrict__ init_state,
               const float* __restrict__ Wp, const float* __restrict__ bp,
               const float* __restrict__ Ws, const float* __restrict__ bs,
               const float* __restrict__ Wd2, const float* __restrict__ bd2,
               const float* __restrict__ bd1,
               float* __restrict__ out)
{
    extern __shared__ uint32_t sm32[];
    uint32_t* A_f  = sm32;                         // 32768 u32 (128KB)
    uint32_t* wbuf = A_f + A_U32;                  // 4*4096 = 16384 u32 (64KB)
    float* bias_s = (float*)(wbuf + 4 * SLAB_U32); // 1536
    float* xcoef  = bias_s + NCOLS;                // 128*8 = 1024
    float* bd1_s  = xcoef + 1024;                  // 64
    float* wd2_s  = bd1_s + D1;                    // 192
    float* bd2_s  = wd2_s + 192;                   // 4
    float* plan_s = bd2_s + 4;                     // 192
    float* st_s   = plan_s + BT * 3;               // 192
    float* gate_s = st_s + BT * 3;                 // 64
    float* d1s    = (float*)(wbuf + 3 * DSLAB_U32);// alias: 4160 floats in wbuf

    const int tid  = threadIdx.x;
    const int lane = tid & 31;
    const int warp = tid >> 5;
    const int gid  = lane >> 2;      // 0..7
    const int tg   = lane & 3;       // 0..3
    const int mw   = warp & 1;       // 32-row half
    const int nw   = warp >> 1;      // 32-col quarter of 128-chunk
    const int bg0  = blockIdx.x * BT;

    // ---- stage constants ----
    for (int i = tid; i < NCOLS; i += NTH) bias_s[i] = g_bias[i];
    if (tid < 128) {
        xcoef[tid * 8 + 0] = Ws[tid * 3 + 0];
        xcoef[tid * 8 + 1] = Ws[tid * 3 + 1];
        xcoef[tid * 8 + 2] = Ws[tid * 3 + 2];
        xcoef[tid * 8 + 3] = bs[tid];
        xcoef[tid * 8 + 4] = Wp[tid * 3 + 0];
        xcoef[tid * 8 + 5] = Wp[tid * 3 + 1];
        xcoef[tid * 8 + 6] = Wp[tid * 3 + 2];
        xcoef[tid * 8 + 7] = bp[tid];
    }
    if (tid < D1)  bd1_s[tid] = bd1[tid];
    if (tid < 192) wd2_s[tid] = Wd2[tid];
    if (tid < 3)   bd2_s[tid] = bd2[tid];
    if (tid < BT * 3) st_s[tid] = init_state[bg0 * 3 + tid];
    if (tid < BT)     gate_s[tid] = gate[bg0 + tid];

    // ---- init hidden: fp32 -> g_hidden and frag hi/lo -> A smem ----
    {
        const float4* src = (const float4*)(init_hidden + (size_t)bg0 * HDIM);
        float4* gh = (float4*)(g_hidden + (size_t)bg0 * HDIM);
        for (int i = tid; i < BT * HDIM / 4; i += NTH) {
            float4 v = src[i];
            gh[i] = v;
            int r = i / (HDIM / 4);
            int h4 = (i - r * (HDIM / 4)) * 4;
            a_write_pair(A_f, r, 128 + h4,     v.x, v.y);
            a_write_pair(A_f, r, 128 + h4 + 2, v.z, v.w);
        }
    }
    __syncthreads();

    // x-producer mapping: thread -> (row b, 32-col group)
    const int xb  = tid & 63;
    const int xcg = (tid >> 6) * 32;

    for (int t = 0; t < T_STEPS; ++t) {
        // ---- stage plan_t ----
        if (tid < BT * 3) {
            int b = tid / 3, j = tid - b * 3;
            plan_s[tid] = plan[(size_t)(bg0 + b) * (T_STEPS * 3) + t * 3 + j];
        }
        __syncthreads();

        // ---- x = state@Ws^T + bs + gate*(plan@Wp^T + bp), frag hi/lo ----
        {
            float s0 = st_s[xb * 3], s1 = st_s[xb * 3 + 1], s2 = st_s[xb * 3 + 2];
            float p0 = plan_s[xb * 3], p1 = plan_s[xb * 3 + 1], p2 = plan_s[xb * 3 + 2];
            float gt = gate_s[xb];
            #pragma unroll 4
            for (int jj = 0; jj < 32; jj += 2) {
                const float* c0 = xcoef + (xcg + jj) * 8;
                const float* c1 = c0 + 8;
                float v0 = fmaf(c0[0], s0, fmaf(c0[1], s1, fmaf(c0[2], s2, c0[3])))
                         + gt * fmaf(c0[4], p0, fmaf(c0[5], p1, fmaf(c0[6], p2, c0[7])));
                float v1 = fmaf(c1[0], s0, fmaf(c1[1], s1, fmaf(c1[2], s2, c1[3])))
                         + gt * fmaf(c1[4], p0, fmaf(c1[5], p1, fmaf(c1[6], p2, c1[7])));
                a_write_pair(A_f, xb, xcg + jj, v0, v1);
            }
        }
        __syncthreads();

        // =============== main GEMM: [64x512] * [512x1536] ===============
        #pragma unroll
        for (int p = 0; p < 3; ++p) {   // prologue: slabs 0,1,2
            const uint32_t* s = g_Wf + (size_t)p * SLAB_U32 + tid * 16;
            uint32_t* d = wbuf + p * SLAB_U32 + tid * 16;
            cp16s(d, s); cp16s(d + 4, s + 4); cp16s(d + 8, s + 8); cp16s(d + 12, s + 12);
            cp_commit();
        }

        int it = 0;
        for (int c = 0; c < NCHUNK; ++c) {
            float acc[2][4][4];
            #pragma unroll
            for (int mt = 0; mt < 2; ++mt)
            #pragma unroll
            for (int nt = 0; nt < 4; ++nt) {
                int col = c * 128 + nw * 32 + nt * 8 + 2 * tg;
                float b0v = bias_s[col], b1v = bias_s[col + 1];
                acc[mt][nt][0] = b0v; acc[mt][nt][1] = b1v;
                acc[mt][nt][2] = b0v; acc[mt][nt][3] = b1v;
            }
            // prefetch oldh for this chunk's epilogue (hides ~L2 latency)
            float oldv[2][4][2];
            if ((tg & 1) == 0) {
                #pragma unroll
                for (int mt = 0; mt < 2; ++mt)
                #pragma unroll
                for (int nt = 0; nt < 4; ++nt) {
                    int h = c * 32 + nw * 8 + nt * 2 + (tg >> 1);
                    size_t gr = (size_t)(bg0 + mw * 32 + mt * 16 + gid) * HDIM + h;
                    oldv[mt][nt][0] = g_hidden[gr];
                    oldv[mt][nt][1] = g_hidden[gr + (size_t)8 * HDIM];
                }
            }

            for (int sl = 0; sl < 16; ++sl, ++it) {
                cp_wait<2>();
                __syncthreads();          // slab `it` visible; reads of it-1 done
                {
                    int pit = it + 3;
                    if (pit < MAIN_SLABS) {
                        const uint32_t* s = g_Wf + (size_t)pit * SLAB_U32 + tid * 16;
                        uint32_t* d = wbuf + (pit & 3) * SLAB_U32 + tid * 16;
                        cp16s(d, s);         cp16s(d + 4, s + 4);
                        cp16s(d + 8, s + 8); cp16s(d + 12, s + 12);
                    }
                    cp_commit();
                }
                const uint32_t* buf = wbuf + (it & 3) * SLAB_U32;

                #pragma unroll
                for (int ksl = 0; ksl < 2; ++ksl) {
                    const uint32_t* bb = buf + ksl * 2048;
                    uint4 b4[4];
                    #pragma unroll
                    for (int nt = 0; nt < 4; ++nt)
                        b4[nt] = *(const uint4*)(bb + (nw * 4 + nt) * 128 + lane * 4);
                    int kstep = sl * 2 + ksl;
                    uint4 ah[2], al[2];
                    #pragma unroll
                    for (int mt = 0; mt < 2; ++mt) {
                        const uint32_t* ab = A_f + kstep * 1024 + (mw * 2 + mt) * 256 + lane * 4;
                        ah[mt] = *(const uint4*)ab;
                        al[mt] = *(const uint4*)(ab + 128);
                    }
                    // term-major: hh, hl, lh — no back-to-back RAW on any acc
                    #pragma unroll
                    for (int mt = 0; mt < 2; ++mt)
                    #pragma unroll
                    for (int nt = 0; nt < 4; ++nt)
                        mma16816(acc[mt][nt], ah[mt].x, ah[mt].y, ah[mt].z, ah[mt].w,
                                 b4[nt].x, b4[nt].y);
                    #pragma unroll
                    for (int mt = 0; mt < 2; ++mt)
                    #pragma unroll
                    for (int nt = 0; nt < 4; ++nt)
                        mma16816(acc[mt][nt], ah[mt].x, ah[mt].y, ah[mt].z, ah[mt].w,
                                 b4[nt].z, b4[nt].w);
                    #pragma unroll
                    for (int mt = 0; mt < 2; ++mt)
                    #pragma unroll
                    for (int nt = 0; nt < 4; ++nt)
                        mma16816(acc[mt][nt], al[mt].x, al[mt].y, al[mt].z, al[mt].w,
                                 b4[nt].x, b4[nt].y);
                }
            }

            // ---- GRU pointwise: even tg has (r,z), odd tg has (s,hn); xor-1 pair ----
            #pragma unroll
            for (int mt = 0; mt < 2; ++mt)
            #pragma unroll
            for (int nt = 0; nt < 4; ++nt) {
                float p0 = __shfl_xor_sync(0xffffffffu, acc[mt][nt][0], 1);
                float p1 = __shfl_xor_sync(0xffffffffu, acc[mt][nt][1], 1);
                float p2 = __shfl_xor_sync(0xffffffffu, acc[mt][nt][2], 1);
                float p3 = __shfl_xor_sync(0xffffffffu, acc[mt][nt][3], 1);
                if ((tg & 1) == 0) {
                    int h = c * 32 + nw * 8 + nt * 2 + (tg >> 1);
                    size_t gr = (size_t)(bg0 + mw * 32 + mt * 16 + gid) * HDIM + h;
                    float rg = sigmoid_f(acc[mt][nt][0]);
                    float zg = sigmoid_f(acc[mt][nt][1]);
                    float ng = tanh_f(p0 + (rg - 1.0f) * p1);   // s + (r-1)*hn
                    g_hidden[gr] = (1.0f - zg) * ng + zg * oldv[mt][nt][0];
                    float rg2 = sigmoid_f(acc[mt][nt][2]);
                    float zg2 = sigmoid_f(acc[mt][nt][3]);
                    float ng2 = tanh_f(p2 + (rg2 - 1.0f) * p3);
                    g_hidden[gr + (size_t)8 * HDIM] =
                        (1.0f - zg2) * ng2 + zg2 * oldv[mt][nt][1];
                }
            }
        }
        __syncthreads();   // all pointwise g_hidden writes done

        // ---- refresh A smem hidden frags (hi/lo) from fp32 g_hidden ----
        {
            const float4* gh = (const float4*)(g_hidden + (size_t)bg0 * HDIM);
            for (int i = tid; i < BT * HDIM / 4; i += NTH) {
                float4 v = gh[i];
                int r = i / (HDIM / 4);
                int h4 = (i - r * (HDIM / 4)) * 4;
                a_write_pair(A_f, r, 128 + h4,     v.x, v.y);
                a_write_pair(A_f, r, 128 + h4 + 2, v.z, v.w);
            }
        }
        __syncthreads();

        // ======= decode GEMM: d1 = elu(hidden@Wd1^T + bd1), [64x64], K=384 =======
        {
            #pragma unroll
            for (int p = 0; p < 2; ++p) {
                const uint32_t* s = g_Wd1f + p * DSLAB_U32 + tid * 8;
                uint32_t* d = wbuf + p * DSLAB_U32 + tid * 8;
                cp16s(d, s); cp16s(d + 4, s + 4);
                cp_commit();
            }
            float accd[2][2][4];
            #pragma unroll
            for (int mt = 0; mt < 2; ++mt)
            #pragma unroll
            for (int nt = 0; nt < 2; ++nt) {
                int col = nw * 16 + nt * 8 + 2 * tg;
                float b0v = bd1_s[col], b1v = bd1_s[col + 1];
                accd[mt][nt][0] = b0v; accd[mt][nt][1] = b1v;
                accd[mt][nt][2] = b0v; accd[mt][nt][3] = b1v;
            }
            for (int s = 0; s < DEC_SLABS; ++s) {
                cp_wait<1>();
                __syncthreads();
                {
                    int p = s + 2;
                    if (p < DEC_SLABS) {
                        const uint32_t* sp = g_Wd1f + p * DSLAB_U32 + tid * 8;
                        uint32_t* d = wbuf + (p % 3) * DSLAB_U32 + tid * 8;
                        cp16s(d, sp); cp16s(d + 4, sp + 4);
                    }
                    cp_commit();
                }
                const uint32_t* buf = wbuf + (s % 3) * DSLAB_U32;
                #pragma unroll
                for (int ksl = 0; ksl < 2; ++ksl) {
                    const uint32_t* bb = buf + ksl * 1024;
                    uint4 b4[2];
                    #pragma unroll
                    for (int nt = 0; nt < 2; ++nt)
                        b4[nt] = *(const uint4*)(bb + (nw * 2 + nt) * 128 + lane * 4);
                    int kstep = 8 + s * 2 + ksl;   // hidden region of A
                    uint4 ah[2], al[2];
                    #pragma unroll
                    for (int mt = 0; mt < 2; ++mt) {
                        const uint32_t* ab = A_f + kstep * 1024 + (mw * 2 + mt) * 256 + lane * 4;
                        ah[mt] = *(const uint4*)ab;
                        al[mt] = *(const uint4*)(ab + 128);
                    }
                    #pragma unroll
                    for (int mt = 0; mt < 2; ++mt)
                    #pragma unroll
                    for (int nt = 0; nt < 2; ++nt)
                        mma16816(accd[mt][nt], ah[mt].x, ah[mt].y, ah[mt].z, ah[mt].w,
                                 b4[nt].x, b4[nt].y);
                    #pragma unroll
                    for (int mt = 0; mt < 2; ++mt)
                    #pragma unroll
                    for (int nt = 0; nt < 2; ++nt)
                        mma16816(accd[mt][nt], ah[mt].x, ah[mt].y, ah[mt].z, ah[mt].w,
                                 b4[nt].z, b4[nt].w);
                    #pragma unroll
                    for (int mt = 0; mt < 2; ++mt)
                    #pragma unroll
                    for (int nt = 0; nt < 2; ++nt)
                        mma16816(accd[mt][nt], al[mt].x, al[mt].y, al[mt].z, al[mt].w,
                                 b4[nt].x, b4[nt].y);
                }
            }
            __syncthreads();   // decode buffers dead before d1s alias is written
            // ELU -> d1s
            #pragma unroll
            for (int mt = 0; mt < 2; ++mt)
            #pragma unroll
            for (int nt = 0; nt < 2; ++nt) {
                int col = nw * 16 + nt * 8 + 2 * tg;
                int row = mw * 32 + mt * 16 + gid;
                d1s[row * D1PAD + col]           = elu_f(accd[mt][nt][0]);
                d1s[row * D1PAD + col + 1]       = elu_f(accd[mt][nt][1]);
                d1s[(row + 8) * D1PAD + col]     = elu_f(accd[mt][nt][2]);
                d1s[(row + 8) * D1PAD + col + 1] = elu_f(accd[mt][nt][3]);
            }
        }
        __syncthreads();

        // ---- decode layer 2 + state update + output ----
        if (tid < BT * 3) {
            int b = tid / 3, j = tid - b * 3;
            const float* w = wd2_s + j * 64;
            const float* d = d1s + b * D1PAD;
            float sum = bd2_s[j];
            #pragma unroll
            for (int k = 0; k < 64; ++k)
                sum = fmaf(d[k], w[k], sum);
            float ns = st_s[tid] + sum;
            st_s[tid] = ns;
            out[(size_t)(bg0 + b) * (T_STEPS * 3) + t * 3 + j] = ns;
        }
        __syncthreads();
    }
}

// ----------------------------------------------------------------------------
extern "C" void kernel_launch(void* const* d_in, const int* in_sizes, int n_in,
                              void* d_out, int out_size)
{
    (void)in_sizes; (void)n_in; (void)out_size;
    const float* init_hidden = (const float*)d_in[0];
    const float* plan        = (const float*)d_in[1];
    const float* gate        = (const float*)d_in[2];
    const float* init_state  = (const float*)d_in[3];
    const float* Wp   = (const float*)d_in[4];
    const float* bp   = (const float*)d_in[5];
    const float* Ws   = (const float*)d_in[6];
    const float* bs   = (const float*)d_in[7];
    const float* W_ih = (const float*)d_in[8];
    const float* b_ih = (const float*)d_in[9];
    const float* W_hh = (const float*)d_in[10];
    const float* b_hh = (const float*)d_in[11];
    const float* Wd1  = (const float*)d_in[12];
    const float* bd1  = (const float*)d_in[13];
    const float* Wd2  = (const float*)d_in[14];
    const float* bd2  = (const float*)d_in[15];
    float* out = (float*)d_out;

    pack_kernel<<<(KTOT * NCOLS + 255) / 256, 256>>>(W_ih, W_hh, b_ih, b_hh, Wd1);

    const int smem_bytes = (A_U32 + 4 * SLAB_U32 + NCOLS + 1024
                            + D1 + 192 + 4 + BT * 3 + BT * 3 + BT) * 4;
    cudaFuncSetAttribute(decoder_kernel,
                         cudaFuncAttributeMaxDynamicSharedMemorySize, smem_bytes);
    decoder_kernel<<<B_TOTAL / BT, NTH, smem_bytes>>>(
        init_hidden, plan, gate, init_state,
        Wp, bp, Ws, bs, Wd2, bd2, bd1, out);
}

// round 9
// speedup vs baseline: 2.1500x; 1.0602x over previous
#include <cuda_runtime.h>
#include <cuda_bf16.h>
#include <cstdint>
#include <cstddef>

// ---------------- problem constants ----------------
#define B_TOTAL 32768
#define T_STEPS 30
#define HDIM    384
#define BT      64          // batch rows per CTA
#define NTH     512         // 16 warps = 2 groups of 8
#define KTOT    512         // [x(128) | hidden(384)]
#define NCOLS   1536        // 384 h * 4 gates (r,z,s,hn), gate-interleaved
#define NCHUNK  12          // 128 cols per chunk
#define SLAB_U32 4096       // 16KB: one slab = 2 ksteps(32 k) x 128 cols, hi+lo fused
#define MAIN_SLABS 192      // 12 chunks * 16 slabs
#define DEC_SLABS  12       // decode K=384 -> 12 slabs of 2 ksteps
#define DSLAB_U32  2048     // 8KB per decode slab
#define D1      64
#define D1PAD   65
#define A_U32   32768       // 32 ksteps * 1024 u32 (frag-ordered, hi+lo)

// ---------------- device scratch (no allocations allowed) ----------------
__device__ uint32_t g_Wf[(size_t)MAIN_SLABS * SLAB_U32];   // 3 MB main-W frags
__device__ uint32_t g_Wd1f[DEC_SLABS * DSLAB_U32];         // 96 KB Wd1 frags
__device__ float    g_bias[NCOLS];
__device__ float    g_hidden[(size_t)B_TOTAL * HDIM];      // fp32 recurrent state

// ---------------- helpers ----------------
__device__ __forceinline__ void cp16s(void* dst, const void* src) {
    unsigned d = (unsigned)__cvta_generic_to_shared(dst);
    asm volatile("cp.async.ca.shared.global [%0], [%1], 16;\n" :: "r"(d), "l"(src));
}
__device__ __forceinline__ void cp_commit() { asm volatile("cp.async.commit_group;\n"); }
template<int N> __device__ __forceinline__ void cp_wait() {
    asm volatile("cp.async.wait_group %0;\n" :: "n"(N));
}
// group-scoped named barrier (256 threads)
__device__ __forceinline__ void barg(int id) {
    asm volatile("bar.sync %0, %1;" :: "r"(id), "r"(256) : "memory");
}
__device__ __forceinline__ float sigmoid_f(float x) { return 1.0f / (1.0f + __expf(-x)); }
__device__ __forceinline__ float tanh_f(float x) {
    float e2 = __expf(2.0f * x);
    return 1.0f - 2.0f / (e2 + 1.0f);
}
__device__ __forceinline__ float elu_f(float x) {
    return x > 0.0f ? x : (__expf(x) - 1.0f);
}
__device__ __forceinline__ void mma16816(float* c,
    uint32_t a0, uint32_t a1, uint32_t a2, uint32_t a3, uint32_t b0, uint32_t b1)
{
    asm volatile(
        "mma.sync.aligned.m16n8k16.row.col.f32.bf16.bf16.f32 "
        "{%0,%1,%2,%3}, {%4,%5,%6,%7}, {%8,%9}, {%0,%1,%2,%3};\n"
        : "+f"(c[0]), "+f"(c[1]), "+f"(c[2]), "+f"(c[3])
        : "r"(a0), "r"(a1), "r"(a2), "r"(a3), "r"(b0), "r"(b1));
}

// Write element pair (row, k even, k+1) into frag-ordered A smem (hi + lo).
// A layout (u32): kstep*1024 + mt*256 + [hi:0 | lo:128] + lane*4 + reg
__device__ __forceinline__ void a_write_pair(uint32_t* A, int row, int k,
                                             float v0, float v1)
{
    int kstep = k >> 4, kk = k & 15;
    int mt = row >> 4, r16 = row & 15;
    int gid = r16 & 7, hi8 = r16 >> 3;
    int tg2 = (kk & 7) >> 1, k8 = kk >> 3;
    int reg = hi8 + 2 * k8;
    int lane = gid * 4 + tg2;
    uint32_t uidx = kstep * 1024 + mt * 256 + lane * 4 + reg;
    __nv_bfloat16 h0 = __float2bfloat16(v0);
    __nv_bfloat16 h1 = __float2bfloat16(v1);
    unsigned hw = (unsigned)__bfloat16_as_ushort(h0)
                | ((unsigned)__bfloat16_as_ushort(h1) << 16);
    unsigned lw = (unsigned)__bfloat16_as_ushort(__float2bfloat16(v0 - __bfloat162float(h0)))
                | ((unsigned)__bfloat16_as_ushort(__float2bfloat16(v1 - __bfloat162float(h1))) << 16);
    A[uidx]       = hw;
    A[uidx + 128] = lw;
}

// ----------------------------------------------------------------------------
// Pack: W = [W_ih | W_hh] -> bf16 hi/lo, fused-fragment order (unchanged).
// ----------------------------------------------------------------------------
__global__ void pack_kernel(const float* __restrict__ W_ih,
                            const float* __restrict__ W_hh,
                            const float* __restrict__ b_ih,
                            const float* __restrict__ b_hh,
                            const float* __restrict__ Wd1)
{
    int idx = blockIdx.x * blockDim.x + threadIdx.x;
    __nv_bfloat16* Wf16   = (__nv_bfloat16*)g_Wf;
    __nv_bfloat16* Wd1f16 = (__nv_bfloat16*)g_Wd1f;

    if (idx < KTOT * NCOLS) {
        int k = idx / NCOLS;
        int col = idx - k * NCOLS;
        int chunk = col >> 7, q = col & 127;
        int i = q >> 2, g = q & 3, h = chunk * 32 + i;
        float v;
        if (g < 3) {
            int row = g * HDIM + h;
            v = (k < 128) ? W_ih[row * 128 + k] : W_hh[row * HDIM + (k - 128)];
        } else {
            v = (k < 128) ? 0.0f : W_hh[(2 * HDIM + h) * HDIM + (k - 128)];
        }
        __nv_bfloat16 hi = __float2bfloat16(v);
        __nv_bfloat16 lo = __float2bfloat16(v - __bfloat162float(hi));
        int kstep = k >> 4, kk = k & 15;
        int reg = kk >> 3, tg2 = (kk & 7) >> 1, half = kk & 1;
        int ntg = q >> 3, n = q & 7;
        int lane = n * 4 + tg2;
        size_t base = (size_t)(chunk * 32 + kstep) * 2048;
        size_t uhi = base + ntg * 128 + lane * 4 + reg;
        Wf16[uhi * 2 + half]       = hi;
        Wf16[(uhi + 2) * 2 + half] = lo;
    }
    if (idx < HDIM * D1) {
        int k = idx >> 6, j = idx & 63;
        float v = Wd1[j * HDIM + k];
        __nv_bfloat16 hi = __float2bfloat16(v);
        __nv_bfloat16 lo = __float2bfloat16(v - __bfloat162float(hi));
        int kstep = k >> 4, kk = k & 15;
        int reg = kk >> 3, tg2 = (kk & 7) >> 1, half = kk & 1;
        int ntg = j >> 3, n = j & 7;
        int lane = n * 4 + tg2;
        size_t uhi = (size_t)kstep * 1024 + ntg * 128 + lane * 4 + reg;
        Wd1f16[uhi * 2 + half]       = hi;
        Wd1f16[(uhi + 2) * 2 + half] = lo;
    }
    if (idx < NCOLS) {
        int c = idx >> 7, q = idx & 127, i = q >> 2, g = q & 3;
        int h = c * 32 + i;
        float bv;
        if (g == 3) bv = b_hh[2 * HDIM + h];
        else        bv = b_ih[g * HDIM + h] + b_hh[g * HDIM + h];
        g_bias[idx] = bv;
    }
}

// ----------------------------------------------------------------------------
// Persistent per-tile decoder, 16 warps = 2 groups of 8 on 2 chunks at a time.
// Group-local warps: mw = gwarp&1 (2 mtiles of 16 rows), nw = gwarp>>1 (4 ntiles).
// ----------------------------------------------------------------------------
__global__ void __launch_bounds__(NTH, 1)
decoder_kernel(const float* __restrict__ init_hidden,
               const float* __restrict__ plan,
               const float* __restrict__ gate,
               const float* __restrict__ init_state,
               const float* __restrict__ Wp, const float* __restrict__ bp,
               const float* __restrict__ Ws, const float* __restrict__ bs,
               const float* __restrict__ Wd2, const float* __restrict__ bd2,
               const float* __restrict__ bd1,
               float* __restrict__ out)
{
    extern __shared__ uint32_t sm32[];
    uint32_t* A_f  = sm32;                         // 32768 u32 (128KB)
    uint32_t* wbuf = A_f + A_U32;                  // 2 groups * 2 slabs * 4096 = 16384 u32
    float* d1s    = (float*)(wbuf + 4 * SLAB_U32); // 64*65 = 4160
    float* bias_s = d1s + BT * D1PAD;              // 1536
    float* xcoef  = bias_s + NCOLS;                // 1024
    float* bd1_s  = xcoef + 1024;                  // 64
    float* wd2_s  = bd1_s + D1;                    // 192
    float* bd2_s  = wd2_s + 192;                   // 4
    float* plan_s = bd2_s + 4;                     // 192
    float* st_s   = plan_s + BT * 3;               // 192
    float* gate_s = st_s + BT * 3;                 // 64
    float* red    = (float*)A_f;                   // decode reduction: x-ksteps area (dead)

    const int tid   = threadIdx.x;
    const int lane  = tid & 31;
    const int warp  = tid >> 5;
    const int group = warp >> 3;     // 0 or 1
    const int gwarp = warp & 7;      // warp within group
    const int gtid  = tid & 255;     // thread within group
    const int gid   = lane >> 2;     // 0..7
    const int tg    = lane & 3;      // 0..3
    const int mw    = gwarp & 1;     // 32-row half
    const int nw    = gwarp >> 1;    // 32-col quarter of 128-chunk
    const int bg0   = blockIdx.x * BT;
    uint32_t* ring  = wbuf + group * 2 * SLAB_U32;

    // ---- stage constants ----
    for (int i = tid; i < NCOLS; i += NTH) bias_s[i] = g_bias[i];
    if (tid < 128) {
        xcoef[tid * 8 + 0] = Ws[tid * 3 + 0];
        xcoef[tid * 8 + 1] = Ws[tid * 3 + 1];
        xcoef[tid * 8 + 2] = Ws[tid * 3 + 2];
        xcoef[tid * 8 + 3] = bs[tid];
        xcoef[tid * 8 + 4] = Wp[tid * 3 + 0];
        xcoef[tid * 8 + 5] = Wp[tid * 3 + 1];
        xcoef[tid * 8 + 6] = Wp[tid * 3 + 2];
        xcoef[tid * 8 + 7] = bp[tid];
    }
    if (tid < D1)  bd1_s[tid] = bd1[tid];
    if (tid < 192) wd2_s[tid] = Wd2[tid];
    if (tid < 3)   bd2_s[tid] = bd2[tid];
    if (tid < BT * 3) st_s[tid] = init_state[bg0 * 3 + tid];
    if (tid < BT)     gate_s[tid] = gate[bg0 + tid];

    // ---- init hidden: fp32 -> g_hidden and frag hi/lo -> A smem ----
    {
        const float4* src = (const float4*)(init_hidden + (size_t)bg0 * HDIM);
        float4* gh = (float4*)(g_hidden + (size_t)bg0 * HDIM);
        for (int i = tid; i < BT * HDIM / 4; i += NTH) {
            float4 v = src[i];
            gh[i] = v;
            int r = i / (HDIM / 4);
            int h4 = (i - r * (HDIM / 4)) * 4;
            a_write_pair(A_f, r, 128 + h4,     v.x, v.y);
            a_write_pair(A_f, r, 128 + h4 + 2, v.z, v.w);
        }
    }
    __syncthreads();

    // x-producer mapping: 512 threads -> (row b, 16-col group)
    const int xb  = tid & 63;
    const int xcg = (tid >> 6) * 16;

    for (int t = 0; t < T_STEPS; ++t) {
        // ---- stage plan_t ----
        if (tid < BT * 3) {
            int b = tid / 3, j = tid - b * 3;
            plan_s[tid] = plan[(size_t)(bg0 + b) * (T_STEPS * 3) + t * 3 + j];
        }
        __syncthreads();

        // ---- x = state@Ws^T + bs + gate*(plan@Wp^T + bp), frag hi/lo ----
        {
            float s0 = st_s[xb * 3], s1 = st_s[xb * 3 + 1], s2 = st_s[xb * 3 + 2];
            float p0 = plan_s[xb * 3], p1 = plan_s[xb * 3 + 1], p2 = plan_s[xb * 3 + 2];
            float gt = gate_s[xb];
            #pragma unroll 4
            for (int jj = 0; jj < 16; jj += 2) {
                const float* c0 = xcoef + (xcg + jj) * 8;
                const float* c1 = c0 + 8;
                float v0 = fmaf(c0[0], s0, fmaf(c0[1], s1, fmaf(c0[2], s2, c0[3])))
                         + gt * fmaf(c0[4], p0, fmaf(c0[5], p1, fmaf(c0[6], p2, c0[7])));
                float v1 = fmaf(c1[0], s0, fmaf(c1[1], s1, fmaf(c1[2], s2, c1[3])))
                         + gt * fmaf(c1[4], p0, fmaf(c1[5], p1, fmaf(c1[6], p2, c1[7])));
                a_write_pair(A_f, xb, xcg + jj, v0, v1);
            }
        }
        __syncthreads();

        // ======= main GEMM: 2 groups, group g owns chunks 2*cp+g =======
        // prologue: group's first slab (chunk=group, sl=0)
        {
            const uint32_t* s = g_Wf + (size_t)(group * 16) * SLAB_U32 + gtid * 16;
            uint32_t* d = ring + gtid * 16;
            cp16s(d, s); cp16s(d + 4, s + 4); cp16s(d + 8, s + 8); cp16s(d + 12, s + 12);
            cp_commit();
        }

        int it = 0;
        for (int cp = 0; cp < 6; ++cp) {
            const int c = 2 * cp + group;
            float acc[2][4][4];
            #pragma unroll
            for (int mt = 0; mt < 2; ++mt)
            #pragma unroll
            for (int nt = 0; nt < 4; ++nt) {
                int col = c * 128 + nw * 32 + nt * 8 + 2 * tg;
                float b0v = bias_s[col], b1v = bias_s[col + 1];
                acc[mt][nt][0] = b0v; acc[mt][nt][1] = b1v;
                acc[mt][nt][2] = b0v; acc[mt][nt][3] = b1v;
            }
            // prefetch oldh for this chunk's epilogue
            float oldv[2][4][2];
            if ((tg & 1) == 0) {
                #pragma unroll
                for (int mt = 0; mt < 2; ++mt)
                #pragma unroll
                for (int nt = 0; nt < 4; ++nt) {
                    int h = c * 32 + nw * 8 + nt * 2 + (tg >> 1);
                    size_t gr = (size_t)(bg0 + mw * 32 + mt * 16 + gid) * HDIM + h;
                    oldv[mt][nt][0] = g_hidden[gr];
                    oldv[mt][nt][1] = g_hidden[gr + (size_t)8 * HDIM];
                }
            }

            for (int sl = 0; sl < 16; ++sl, ++it) {
                cp_wait<0>();
                barg(group + 1);          // slab `it` fully written; prev buffer free
                {
                    int ni = it + 1;
                    if (ni < 96) {
                        int slab = (2 * (ni >> 4) + group) * 16 + (ni & 15);
                        const uint32_t* s = g_Wf + (size_t)slab * SLAB_U32 + gtid * 16;
                        uint32_t* d = ring + (ni & 1) * SLAB_U32 + gtid * 16;
                        cp16s(d, s);         cp16s(d + 4, s + 4);
                        cp16s(d + 8, s + 8); cp16s(d + 12, s + 12);
                    }
                    cp_commit();
                }
                const uint32_t* buf = ring + (it & 1) * SLAB_U32;

                #pragma unroll
                for (int ksl = 0; ksl < 2; ++ksl) {
                    const uint32_t* bb = buf + ksl * 2048;
                    uint4 b4[4];
                    #pragma unroll
                    for (int nt = 0; nt < 4; ++nt)
                        b4[nt] = *(const uint4*)(bb + (nw * 4 + nt) * 128 + lane * 4);
                    int kstep = sl * 2 + ksl;
                    uint4 ah[2], al[2];
                    #pragma unroll
                    for (int mt = 0; mt < 2; ++mt) {
                        const uint32_t* ab = A_f + kstep * 1024 + (mw * 2 + mt) * 256 + lane * 4;
                        ah[mt] = *(const uint4*)ab;
                        al[mt] = *(const uint4*)(ab + 128);
                    }
                    // term-major: hh, hl, lh — no back-to-back RAW on any acc
                    #pragma unroll
                    for (int mt = 0; mt < 2; ++mt)
                    #pragma unroll
                    for (int nt = 0; nt < 4; ++nt)
                        mma16816(acc[mt][nt], ah[mt].x, ah[mt].y, ah[mt].z, ah[mt].w,
                                 b4[nt].x, b4[nt].y);
                    #pragma unroll
                    for (int mt = 0; mt < 2; ++mt)
                    #pragma unroll
                    for (int nt = 0; nt < 4; ++nt)
                        mma16816(acc[mt][nt], ah[mt].x, ah[mt].y, ah[mt].z, ah[mt].w,
                                 b4[nt].z, b4[nt].w);
                    #pragma unroll
                    for (int mt = 0; mt < 2; ++mt)
                    #pragma unroll
                    for (int nt = 0; nt < 4; ++nt)
                        mma16816(acc[mt][nt], al[mt].x, al[mt].y, al[mt].z, al[mt].w,
                                 b4[nt].x, b4[nt].y);
                }
            }

            // ---- GRU pointwise (group-local; h ranges disjoint across groups) ----
            #pragma unroll
            for (int mt = 0; mt < 2; ++mt)
            #pragma unroll
            for (int nt = 0; nt < 4; ++nt) {
                float p0 = __shfl_xor_sync(0xffffffffu, acc[mt][nt][0], 1);
                float p1 = __shfl_xor_sync(0xffffffffu, acc[mt][nt][1], 1);
                float p2 = __shfl_xor_sync(0xffffffffu, acc[mt][nt][2], 1);
                float p3 = __shfl_xor_sync(0xffffffffu, acc[mt][nt][3], 1);
                if ((tg & 1) == 0) {
                    int h = c * 32 + nw * 8 + nt * 2 + (tg >> 1);
                    size_t gr = (size_t)(bg0 + mw * 32 + mt * 16 + gid) * HDIM + h;
                    float rg = sigmoid_f(acc[mt][nt][0]);
                    float zg = sigmoid_f(acc[mt][nt][1]);
                    float ng = tanh_f(p0 + (rg - 1.0f) * p1);   // s + (r-1)*hn
                    g_hidden[gr] = (1.0f - zg) * ng + zg * oldv[mt][nt][0];
                    float rg2 = sigmoid_f(acc[mt][nt][2]);
                    float zg2 = sigmoid_f(acc[mt][nt][3]);
                    float ng2 = tanh_f(p2 + (rg2 - 1.0f) * p3);
                    g_hidden[gr + (size_t)8 * HDIM] =
                        (1.0f - zg2) * ng2 + zg2 * oldv[mt][nt][1];
                }
            }
        }
        __syncthreads();   // all pointwise g_hidden writes done (both groups)

        // ---- refresh A smem hidden frags (hi/lo) from fp32 g_hidden ----
        {
            const float4* gh = (const float4*)(g_hidden + (size_t)bg0 * HDIM);
            for (int i = tid; i < BT * HDIM / 4; i += NTH) {
                float4 v = gh[i];
                int r = i / (HDIM / 4);
                int h4 = (i - r * (HDIM / 4)) * 4;
                a_write_pair(A_f, r, 128 + h4,     v.x, v.y);
                a_write_pair(A_f, r, 128 + h4 + 2, v.z, v.w);
            }
        }
        __syncthreads();

        // ======= decode GEMM: K split across groups; group g -> dec slabs g*6.. =======
        float accd[2][2][4];
        {
            // prologue
            {
                const uint32_t* s = g_Wd1f + (size_t)(group * 6) * DSLAB_U32 + gtid * 8;
                uint32_t* d = ring + gtid * 8;
                cp16s(d, s); cp16s(d + 4, s + 4);
                cp_commit();
            }
            #pragma unroll
            for (int mt = 0; mt < 2; ++mt)
            #pragma unroll
            for (int nt = 0; nt < 2; ++nt) {
                float b0v = 0.0f, b1v = 0.0f;
                if (group == 0) {
                    int col = nw * 16 + nt * 8 + 2 * tg;
                    b0v = bd1_s[col]; b1v = bd1_s[col + 1];
                }
                accd[mt][nt][0] = b0v; accd[mt][nt][1] = b1v;
                accd[mt][nt][2] = b0v; accd[mt][nt][3] = b1v;
            }
            for (int s = 0; s < 6; ++s) {
                cp_wait<0>();
                barg(group + 1);
                {
                    int ni = s + 1;
                    if (ni < 6) {
                        const uint32_t* sp = g_Wd1f + (size_t)(group * 6 + ni) * DSLAB_U32 + gtid * 8;
                        uint32_t* d = ring + (ni & 1) * DSLAB_U32 + gtid * 8;
                        cp16s(d, sp); cp16s(d + 4, sp + 4);
                    }
                    cp_commit();
                }
                const uint32_t* buf = ring + (s & 1) * DSLAB_U32;
                #pragma unroll
                for (int ksl = 0; ksl < 2; ++ksl) {
                    const uint32_t* bb = buf + ksl * 1024;
                    uint4 b4[2];
                    #pragma unroll
                    for (int nt = 0; nt < 2; ++nt)
                        b4[nt] = *(const uint4*)(bb + (nw * 2 + nt) * 128 + lane * 4);
                    int kstep = 8 + (group * 6 + s) * 2 + ksl;   // hidden region of A
                    uint4 ah[2], al[2];
                    #pragma unroll
                    for (int mt = 0; mt < 2; ++mt) {
                        const uint32_t* ab = A_f + kstep * 1024 + (mw * 2 + mt) * 256 + lane * 4;
                        ah[mt] = *(const uint4*)ab;
                        al[mt] = *(const uint4*)(ab + 128);
                    }
                    #pragma unroll
                    for (int mt = 0; mt < 2; ++mt)
                    #pragma unroll
                    for (int nt = 0; nt < 2; ++nt)
                        mma16816(accd[mt][nt], ah[mt].x, ah[mt].y, ah[mt].z, ah[mt].w,
                                 b4[nt].x, b4[nt].y);
                    #pragma unroll
                    for (int mt = 0; mt < 2; ++mt)
                    #pragma unroll
                    for (int nt = 0; nt < 2; ++nt)
                        mma16816(accd[mt][nt], ah[mt].x, ah[mt].y, ah[mt].z, ah[mt].w,
                                 b4[nt].z, b4[nt].w);
                    #pragma unroll
                    for (int mt = 0; mt < 2; ++mt)
                    #pragma unroll
                    for (int nt = 0; nt < 2; ++nt)
                        mma16816(accd[mt][nt], al[mt].x, al[mt].y, al[mt].z, al[mt].w,
                                 b4[nt].x, b4[nt].y);
                }
            }
        }
        __syncthreads();   // both groups done: A x-region (red) now dead, safe to write

        if (group == 1) {  // stage partial sums
            int base = (gwarp * 32 + lane) * 16;
            #pragma unroll
            for (int mt = 0; mt < 2; ++mt)
            #pragma unroll
            for (int nt = 0; nt < 2; ++nt) {
                int o = base + (mt * 2 + nt) * 4;
                red[o]     = accd[mt][nt][0];
                red[o + 1] = accd[mt][nt][1];
                red[o + 2] = accd[mt][nt][2];
                red[o + 3] = accd[mt][nt][3];
            }
        }
        __syncthreads();

        if (group == 0) {  // reduce + ELU -> d1s
            int base = (gwarp * 32 + lane) * 16;
            #pragma unroll
            for (int mt = 0; mt < 2; ++mt)
            #pragma unroll
            for (int nt = 0; nt < 2; ++nt) {
                int o = base + (mt * 2 + nt) * 4;
                float v0 = accd[mt][nt][0] + red[o];
                float v1 = accd[mt][nt][1] + red[o + 1];
                float v2 = accd[mt][nt][2] + red[o + 2];
                float v3 = accd[mt][nt][3] + red[o + 3];
                int col = nw * 16 + nt * 8 + 2 * tg;
                int row = mw * 32 + mt * 16 + gid;
                d1s[row * D1PAD + col]           = elu_f(v0);
                d1s[row * D1PAD + col + 1]       = elu_f(v1);
                d1s[(row + 8) * D1PAD + col]     = elu_f(v2);
                d1s[(row + 8) * D1PAD + col + 1] = elu_f(v3);
            }
        }
        __syncthreads();

        // ---- decode layer 2 + state update + output ----
        if (tid < BT * 3) {
            int b = tid / 3, j = tid - b * 3;
            const float* w = wd2_s + j * 64;
            const float* d = d1s + b * D1PAD;
            float sum = bd2_s[j];
            #pragma unroll
            for (int k = 0; k < 64; ++k)
                sum = fmaf(d[k], w[k], sum);
            float ns = st_s[tid] + sum;
            st_s[tid] = ns;
            out[(size_t)(bg0 + b) * (T_STEPS * 3) + t * 3 + j] = ns;
        }
        __syncthreads();
    }
}

// ----------------------------------------------------------------------------
extern "C" void kernel_launch(void* const* d_in, const int* in_sizes, int n_in,
                              void* d_out, int out_size)
{
    (void)in_sizes; (void)n_in; (void)out_size;
    const float* init_hidden = (const float*)d_in[0];
    const float* plan        = (const float*)d_in[1];
    const float* gate        = (const float*)d_in[2];
    const float* init_state  = (const float*)d_in[3];
    const float* Wp   = (const float*)d_in[4];
    const float* bp   = (const float*)d_in[5];
    const float* Ws   = (const float*)d_in[6];
    const float* bs   = (const float*)d_in[7];
    const float* W_ih = (const float*)d_in[8];
    const float* b_ih = (const float*)d_in[9];
    const float* W_hh = (const float*)d_in[10];
    const float* b_hh = (const float*)d_in[11];
    const float* Wd1  = (const float*)d_in[12];
    const float* bd1  = (const float*)d_in[13];
    const float* Wd2  = (const float*)d_in[14];
    const float* bd2  = (const float*)d_in[15];
    float* out = (float*)d_out;

    pack_kernel<<<(KTOT * NCOLS + 255) / 256, 256>>>(W_ih, W_hh, b_ih, b_hh, Wd1);

    const int smem_bytes = (A_U32 + 4 * SLAB_U32 + BT * D1PAD + NCOLS + 1024
                            + D1 + 192 + 4 + BT * 3 + BT * 3 + BT) * 4;
    cudaFuncSetAttribute(decoder_kernel,
                         cudaFuncAttributeMaxDynamicSharedMemorySize, smem_bytes);
    decoder_kernel<<<B_TOTAL / BT, NTH, smem_bytes>>>(
        init_hidden, plan, gate, init_state,
        Wp, bp, Ws, bs, Wd2, bd2, bd1, out);
}

// round 10
// speedup vs baseline: 3.6684x; 1.7062x over previous
#include <cuda_runtime.h>
#include <cuda_bf16.h>
#include <cstdint>
#include <cstddef>

// ---------------- problem constants ----------------
#define B_TOTAL 32768
#define T_STEPS 30
#define HDIM    384
#define BT      64          // batch rows per CTA
#define NTH     512         // 16 warps = 2 groups of 8
#define KTOT    512         // [x(128) | hidden(384)]
#define NCOLS   1536        // 384 h * 4 gates (r,z,s,hn), gate-interleaved
#define NCHUNK  12          // 128 cols per chunk
#define SLAB_U32 4096       // one slab = 2 ksteps(32 k) x 128 cols, hi+lo fused
#define MAIN_SLABS 192      // 12 chunks * 16 slabs
#define DEC_SLABS  12
#define DSLAB_U32  2048
#define D1      64
#define D1PAD   65
#define A_U32   32768       // 32 ksteps * 1024 u32 (frag-ordered, hi+lo)
#define CHUNK_U32 65536     // 16 slabs * 4096 u32 per 128-col chunk

// ---------------- device scratch (no allocations allowed) ----------------
__device__ uint32_t g_Wf[(size_t)MAIN_SLABS * SLAB_U32];   // 3 MB main-W frags
__device__ uint32_t g_Wd1f[DEC_SLABS * DSLAB_U32];         // 96 KB Wd1 frags
__device__ float    g_bias[NCOLS];
__device__ float    g_hidden[(size_t)B_TOTAL * HDIM];      // fp32 recurrent state

// ---------------- helpers ----------------
__device__ __forceinline__ float sigmoid_f(float x) { return 1.0f / (1.0f + __expf(-x)); }
__device__ __forceinline__ float tanh_f(float x) {
    float e2 = __expf(2.0f * x);
    return 1.0f - 2.0f / (e2 + 1.0f);
}
__device__ __forceinline__ float elu_f(float x) {
    return x > 0.0f ? x : (__expf(x) - 1.0f);
}
__device__ __forceinline__ void mma16816(float* c,
    uint32_t a0, uint32_t a1, uint32_t a2, uint32_t a3, uint32_t b0, uint32_t b1)
{
    asm volatile(
        "mma.sync.aligned.m16n8k16.row.col.f32.bf16.bf16.f32 "
        "{%0,%1,%2,%3}, {%4,%5,%6,%7}, {%8,%9}, {%0,%1,%2,%3};\n"
        : "+f"(c[0]), "+f"(c[1]), "+f"(c[2]), "+f"(c[3])
        : "r"(a0), "r"(a1), "r"(a2), "r"(a3), "r"(b0), "r"(b1));
}

// Write element pair (row, k even, k+1) into frag-ordered A smem (hi + lo).
// A layout (u32): kstep*1024 + mt*256 + [hi:0 | lo:128] + lane*4 + reg
__device__ __forceinline__ void a_write_pair(uint32_t* A, int row, int k,
                                             float v0, float v1)
{
    int kstep = k >> 4, kk = k & 15;
    int mt = row >> 4, r16 = row & 15;
    int gid = r16 & 7, hi8 = r16 >> 3;
    int tg2 = (kk & 7) >> 1, k8 = kk >> 3;
    int reg = hi8 + 2 * k8;
    int lane = gid * 4 + tg2;
    uint32_t uidx = kstep * 1024 + mt * 256 + lane * 4 + reg;
    __nv_bfloat16 h0 = __float2bfloat16(v0);
    __nv_bfloat16 h1 = __float2bfloat16(v1);
    unsigned hw = (unsigned)__bfloat16_as_ushort(h0)
                | ((unsigned)__bfloat16_as_ushort(h1) << 16);
    unsigned lw = (unsigned)__bfloat16_as_ushort(__float2bfloat16(v0 - __bfloat162float(h0)))
                | ((unsigned)__bfloat16_as_ushort(__float2bfloat16(v1 - __bfloat162float(h1))) << 16);
    A[uidx]       = hw;
    A[uidx + 128] = lw;
}

// ----------------------------------------------------------------------------
// Pack: W = [W_ih | W_hh] -> bf16 hi/lo, fused-fragment order (unchanged).
// ----------------------------------------------------------------------------
__global__ void pack_kernel(const float* __restrict__ W_ih,
                            const float* __restrict__ W_hh,
                            const float* __restrict__ b_ih,
                            const float* __restrict__ b_hh,
                            const float* __restrict__ Wd1)
{
    int idx = blockIdx.x * blockDim.x + threadIdx.x;
    __nv_bfloat16* Wf16   = (__nv_bfloat16*)g_Wf;
    __nv_bfloat16* Wd1f16 = (__nv_bfloat16*)g_Wd1f;

    if (idx < KTOT * NCOLS) {
        int k = idx / NCOLS;
        int col = idx - k * NCOLS;
        int chunk = col >> 7, q = col & 127;
        int i = q >> 2, g = q & 3, h = chunk * 32 + i;
        float v;
        if (g < 3) {
            int row = g * HDIM + h;
            v = (k < 128) ? W_ih[row * 128 + k] : W_hh[row * HDIM + (k - 128)];
        } else {
            v = (k < 128) ? 0.0f : W_hh[(2 * HDIM + h) * HDIM + (k - 128)];
        }
        __nv_bfloat16 hi = __float2bfloat16(v);
        __nv_bfloat16 lo = __float2bfloat16(v - __bfloat162float(hi));
        int kstep = k >> 4, kk = k & 15;
        int reg = kk >> 3, tg2 = (kk & 7) >> 1, half = kk & 1;
        int ntg = q >> 3, n = q & 7;
        int lane = n * 4 + tg2;
        size_t base = (size_t)(chunk * 32 + kstep) * 2048;
        size_t uhi = base + ntg * 128 + lane * 4 + reg;
        Wf16[uhi * 2 + half]       = hi;
        Wf16[(uhi + 2) * 2 + half] = lo;
    }
    if (idx < HDIM * D1) {
        int k = idx >> 6, j = idx & 63;
        float v = Wd1[j * HDIM + k];
        __nv_bfloat16 hi = __float2bfloat16(v);
        __nv_bfloat16 lo = __float2bfloat16(v - __bfloat162float(hi));
        int kstep = k >> 4, kk = k & 15;
        int reg = kk >> 3, tg2 = (kk & 7) >> 1, half = kk & 1;
        int ntg = j >> 3, n = j & 7;
        int lane = n * 4 + tg2;
        size_t uhi = (size_t)kstep * 1024 + ntg * 128 + lane * 4 + reg;
        Wd1f16[uhi * 2 + half]       = hi;
        Wd1f16[(uhi + 2) * 2 + half] = lo;
    }
    if (idx < NCOLS) {
        int c = idx >> 7, q = idx & 127, i = q >> 2, g = q & 3;
        int h = c * 32 + i;
        float bv;
        if (g == 3) bv = b_hh[2 * HDIM + h];
        else        bv = b_ih[g * HDIM + h] + b_hh[g * HDIM + h];
        g_bias[idx] = bv;
    }
}

// ----------------------------------------------------------------------------
// Persistent per-tile decoder. B operands stream directly from L2 via LDG.128
// in fragment order (no smem staging, no mainloop barriers). 2 groups of 8
// warps work on 2 chunks concurrently; group warps: mw = gwarp&1, nw = gwarp>>1.
// ----------------------------------------------------------------------------
__global__ void __launch_bounds__(NTH, 1)
decoder_kernel(const float* __restrict__ init_hidden,
               const float* __restrict__ plan,
               const float* __restrict__ gate,
               const float* __restrict__ init_state,
               const float* __restrict__ Wp, const float* __restrict__ bp,
               const float* __restrict__ Ws, const float* __restrict__ bs,
               const float* __restrict__ Wd2, const float* __restrict__ bd2,
               const float* __restrict__ bd1,
               float* __restrict__ out)
{
    extern __shared__ uint32_t sm32[];
    uint32_t* A_f  = sm32;                         // 32768 u32 (128KB)
    float* d1s    = (float*)(A_f + A_U32);         // 64*65 = 4160
    float* bias_s = d1s + BT * D1PAD;              // 1536
    float* xcoef  = bias_s + NCOLS;                // 1024
    float* bd1_s  = xcoef + 1024;                  // 64
    float* wd2_s  = bd1_s + D1;                    // 192
    float* bd2_s  = wd2_s + 192;                   // 4
    float* plan_s = bd2_s + 4;                     // 192
    float* st_s   = plan_s + BT * 3;               // 192
    float* gate_s = st_s + BT * 3;                 // 64
    float* red    = (float*)A_f;                   // decode reduction: x-kstep area (dead)

    const int tid   = threadIdx.x;
    const int lane  = tid & 31;
    const int warp  = tid >> 5;
    const int group = warp >> 3;     // 0 or 1
    const int gwarp = warp & 7;      // warp within group
    const int gid   = lane >> 2;     // 0..7
    const int tg    = lane & 3;      // 0..3
    const int mw    = gwarp & 1;     // 32-row half
    const int nw    = gwarp >> 1;    // 32-col quarter of 128-chunk
    const int bg0   = blockIdx.x * BT;
    const uint32_t woff  = (uint32_t)(nw * 512 + lane * 4);   // main B warp offset
    const uint32_t dwoff = (uint32_t)(nw * 256 + lane * 4);   // decode B warp offset

    // ---- stage constants ----
    for (int i = tid; i < NCOLS; i += NTH) bias_s[i] = g_bias[i];
    if (tid < 128) {
        xcoef[tid * 8 + 0] = Ws[tid * 3 + 0];
        xcoef[tid * 8 + 1] = Ws[tid * 3 + 1];
        xcoef[tid * 8 + 2] = Ws[tid * 3 + 2];
        xcoef[tid * 8 + 3] = bs[tid];
        xcoef[tid * 8 + 4] = Wp[tid * 3 + 0];
        xcoef[tid * 8 + 5] = Wp[tid * 3 + 1];
        xcoef[tid * 8 + 6] = Wp[tid * 3 + 2];
        xcoef[tid * 8 + 7] = bp[tid];
    }
    if (tid < D1)  bd1_s[tid] = bd1[tid];
    if (tid < 192) wd2_s[tid] = Wd2[tid];
    if (tid < 3)   bd2_s[tid] = bd2[tid];
    if (tid < BT * 3) st_s[tid] = init_state[bg0 * 3 + tid];
    if (tid < BT)     gate_s[tid] = gate[bg0 + tid];

    // ---- init hidden: fp32 -> g_hidden and frag hi/lo -> A smem ----
    {
        const float4* src = (const float4*)(init_hidden + (size_t)bg0 * HDIM);
        float4* gh = (float4*)(g_hidden + (size_t)bg0 * HDIM);
        for (int i = tid; i < BT * HDIM / 4; i += NTH) {
            float4 v = src[i];
            gh[i] = v;
            int r = i / (HDIM / 4);
            int h4 = (i - r * (HDIM / 4)) * 4;
            a_write_pair(A_f, r, 128 + h4,     v.x, v.y);
            a_write_pair(A_f, r, 128 + h4 + 2, v.z, v.w);
        }
    }
    __syncthreads();

    // x-producer mapping: 512 threads -> (row b, 16-col group)
    const int xb  = tid & 63;
    const int xcg = (tid >> 6) * 16;

    for (int t = 0; t < T_STEPS; ++t) {
        // ---- stage plan_t ----
        if (tid < BT * 3) {
            int b = tid / 3, j = tid - b * 3;
            plan_s[tid] = plan[(size_t)(bg0 + b) * (T_STEPS * 3) + t * 3 + j];
        }
        __syncthreads();

        // ---- x = state@Ws^T + bs + gate*(plan@Wp^T + bp), frag hi/lo ----
        {
            float s0 = st_s[xb * 3], s1 = st_s[xb * 3 + 1], s2 = st_s[xb * 3 + 2];
            float p0 = plan_s[xb * 3], p1 = plan_s[xb * 3 + 1], p2 = plan_s[xb * 3 + 2];
            float gt = gate_s[xb];
            #pragma unroll 4
            for (int jj = 0; jj < 16; jj += 2) {
                const float* c0 = xcoef + (xcg + jj) * 8;
                const float* c1 = c0 + 8;
                float v0 = fmaf(c0[0], s0, fmaf(c0[1], s1, fmaf(c0[2], s2, c0[3])))
                         + gt * fmaf(c0[4], p0, fmaf(c0[5], p1, fmaf(c0[6], p2, c0[7])));
                float v1 = fmaf(c1[0], s0, fmaf(c1[1], s1, fmaf(c1[2], s2, c1[3])))
                         + gt * fmaf(c1[4], p0, fmaf(c1[5], p1, fmaf(c1[6], p2, c1[7])));
                a_write_pair(A_f, xb, xcg + jj, v0, v1);
            }
        }
        __syncthreads();

        // ======= main GEMM: 2 groups, group g owns chunks 2*cp+g; B via LDG =======
        uint4 bn[4];   // prefetched B for next kstep
        {
            const uint32_t* p = g_Wf + (size_t)group * CHUNK_U32 + woff;
            #pragma unroll
            for (int nt = 0; nt < 4; ++nt)
                bn[nt] = __ldg((const uint4*)(p + nt * 128));
        }

        for (int cp = 0; cp < 6; ++cp) {
            const int c = 2 * cp + group;
            float acc[2][4][4];
            #pragma unroll
            for (int mt = 0; mt < 2; ++mt)
            #pragma unroll
            for (int nt = 0; nt < 4; ++nt) {
                int col = c * 128 + nw * 32 + nt * 8 + 2 * tg;
                float b0v = bias_s[col], b1v = bias_s[col + 1];
                acc[mt][nt][0] = b0v; acc[mt][nt][1] = b1v;
                acc[mt][nt][2] = b0v; acc[mt][nt][3] = b1v;
            }
            // prefetch oldh for this chunk's epilogue
            float oldv[2][4][2];
            if ((tg & 1) == 0) {
                #pragma unroll
                for (int mt = 0; mt < 2; ++mt)
                #pragma unroll
                for (int nt = 0; nt < 4; ++nt) {
                    int h = c * 32 + nw * 8 + nt * 2 + (tg >> 1);
                    size_t gr = (size_t)(bg0 + mw * 32 + mt * 16 + gid) * HDIM + h;
                    oldv[mt][nt][0] = g_hidden[gr];
                    oldv[mt][nt][1] = g_hidden[gr + (size_t)8 * HDIM];
                }
            }

            for (int kstep = 0; kstep < 32; ++kstep) {
                uint4 bc[4] = {bn[0], bn[1], bn[2], bn[3]};
                // prefetch B for next kstep (crossing chunk boundary when needed)
                {
                    size_t naddr;
                    if (kstep < 31)
                        naddr = (size_t)c * CHUNK_U32 + (size_t)(kstep + 1) * 2048;
                    else if (cp < 5)
                        naddr = (size_t)(c + 2) * CHUNK_U32;
                    else
                        naddr = (size_t)group * CHUNK_U32;   // harmless warm reload
                    const uint32_t* p = g_Wf + naddr + woff;
                    #pragma unroll
                    for (int nt = 0; nt < 4; ++nt)
                        bn[nt] = __ldg((const uint4*)(p + nt * 128));
                }
                uint4 ah[2], al[2];
                #pragma unroll
                for (int mt = 0; mt < 2; ++mt) {
                    const uint32_t* ab = A_f + kstep * 1024 + (mw * 2 + mt) * 256 + lane * 4;
                    ah[mt] = *(const uint4*)ab;
                    al[mt] = *(const uint4*)(ab + 128);
                }
                // term-major: hh, hl, lh — no back-to-back RAW on any acc
                #pragma unroll
                for (int mt = 0; mt < 2; ++mt)
                #pragma unroll
                for (int nt = 0; nt < 4; ++nt)
                    mma16816(acc[mt][nt], ah[mt].x, ah[mt].y, ah[mt].z, ah[mt].w,
                             bc[nt].x, bc[nt].y);
                #pragma unroll
                for (int mt = 0; mt < 2; ++mt)
                #pragma unroll
                for (int nt = 0; nt < 4; ++nt)
                    mma16816(acc[mt][nt], ah[mt].x, ah[mt].y, ah[mt].z, ah[mt].w,
                             bc[nt].z, bc[nt].w);
                #pragma unroll
                for (int mt = 0; mt < 2; ++mt)
                #pragma unroll
                for (int nt = 0; nt < 4; ++nt)
                    mma16816(acc[mt][nt], al[mt].x, al[mt].y, al[mt].z, al[mt].w,
                             bc[nt].x, bc[nt].y);
            }

            // ---- GRU pointwise (group-local; h ranges disjoint across groups) ----
            #pragma unroll
            for (int mt = 0; mt < 2; ++mt)
            #pragma unroll
            for (int nt = 0; nt < 4; ++nt) {
                float p0 = __shfl_xor_sync(0xffffffffu, acc[mt][nt][0], 1);
                float p1 = __shfl_xor_sync(0xffffffffu, acc[mt][nt][1], 1);
                float p2 = __shfl_xor_sync(0xffffffffu, acc[mt][nt][2], 1);
                float p3 = __shfl_xor_sync(0xffffffffu, acc[mt][nt][3], 1);
                if ((tg & 1) == 0) {
                    int h = c * 32 + nw * 8 + nt * 2 + (tg >> 1);
                    size_t gr = (size_t)(bg0 + mw * 32 + mt * 16 + gid) * HDIM + h;
                    float rg = sigmoid_f(acc[mt][nt][0]);
                    float zg = sigmoid_f(acc[mt][nt][1]);
                    float ng = tanh_f(p0 + (rg - 1.0f) * p1);   // s + (r-1)*hn
                    g_hidden[gr] = (1.0f - zg) * ng + zg * oldv[mt][nt][0];
                    float rg2 = sigmoid_f(acc[mt][nt][2]);
                    float zg2 = sigmoid_f(acc[mt][nt][3]);
                    float ng2 = tanh_f(p2 + (rg2 - 1.0f) * p3);
                    g_hidden[gr + (size_t)8 * HDIM] =
                        (1.0f - zg2) * ng2 + zg2 * oldv[mt][nt][1];
                }
            }
        }
        __syncthreads();   // all pointwise g_hidden writes done (both groups)

        // ---- refresh A smem hidden frags (hi/lo) from fp32 g_hidden ----
        {
            const float4* gh = (const float4*)(g_hidden + (size_t)bg0 * HDIM);
            for (int i = tid; i < BT * HDIM / 4; i += NTH) {
                float4 v = gh[i];
                int r = i / (HDIM / 4);
                int h4 = (i - r * (HDIM / 4)) * 4;
                a_write_pair(A_f, r, 128 + h4,     v.x, v.y);
                a_write_pair(A_f, r, 128 + h4 + 2, v.z, v.w);
            }
        }
        __syncthreads();

        // ======= decode GEMM: K split across groups; B via LDG =======
        float accd[2][2][4];
        {
            uint4 dbn[2];
            {
                const uint32_t* p = g_Wd1f + (size_t)(group * 12) * 1024 + dwoff;
                #pragma unroll
                for (int nt = 0; nt < 2; ++nt)
                    dbn[nt] = __ldg((const uint4*)(p + nt * 128));
            }
            #pragma unroll
            for (int mt = 0; mt < 2; ++mt)
            #pragma unroll
            for (int nt = 0; nt < 2; ++nt) {
                float b0v = 0.0f, b1v = 0.0f;
                if (group == 0) {
                    int col = nw * 16 + nt * 8 + 2 * tg;
                    b0v = bd1_s[col]; b1v = bd1_s[col + 1];
                }
                accd[mt][nt][0] = b0v; accd[mt][nt][1] = b1v;
                accd[mt][nt][2] = b0v; accd[mt][nt][3] = b1v;
            }
            for (int d = 0; d < 12; ++d) {
                uint4 dbc[2] = {dbn[0], dbn[1]};
                {
                    int nd = (d < 11) ? (d + 1) : 0;
                    const uint32_t* p = g_Wd1f + (size_t)(group * 12 + nd) * 1024 + dwoff;
                    #pragma unroll
                    for (int nt = 0; nt < 2; ++nt)
                        dbn[nt] = __ldg((const uint4*)(p + nt * 128));
                }
                int kstep = 8 + group * 12 + d;   // hidden region of A
                uint4 ah[2], al[2];
                #pragma unroll
                for (int mt = 0; mt < 2; ++mt) {
                    const uint32_t* ab = A_f + kstep * 1024 + (mw * 2 + mt) * 256 + lane * 4;
                    ah[mt] = *(const uint4*)ab;
                    al[mt] = *(const uint4*)(ab + 128);
                }
                #pragma unroll
                for (int mt = 0; mt < 2; ++mt)
                #pragma unroll
                for (int nt = 0; nt < 2; ++nt)
                    mma16816(accd[mt][nt], ah[mt].x, ah[mt].y, ah[mt].z, ah[mt].w,
                             dbc[nt].x, dbc[nt].y);
                #pragma unroll
                for (int mt = 0; mt < 2; ++mt)
                #pragma unroll
                for (int nt = 0; nt < 2; ++nt)
                    mma16816(accd[mt][nt], ah[mt].x, ah[mt].y, ah[mt].z, ah[mt].w,
                             dbc[nt].z, dbc[nt].w);
                #pragma unroll
                for (int mt = 0; mt < 2; ++mt)
                #pragma unroll
                for (int nt = 0; nt < 2; ++nt)
                    mma16816(accd[mt][nt], al[mt].x, al[mt].y, al[mt].z, al[mt].w,
                             dbc[nt].x, dbc[nt].y);
            }
        }
        __syncthreads();   // both groups done: A x-region (red) now dead, safe to write

        if (group == 1) {  // stage partial sums
            int base = (gwarp * 32 + lane) * 16;
            #pragma unroll
            for (int mt = 0; mt < 2; ++mt)
            #pragma unroll
            for (int nt = 0; nt < 2; ++nt) {
                int o = base + (mt * 2 + nt) * 4;
                red[o]     = accd[mt][nt][0];
                red[o + 1] = accd[mt][nt][1];
                red[o + 2] = accd[mt][nt][2];
                red[o + 3] = accd[mt][nt][3];
            }
        }
        __syncthreads();

        if (group == 0) {  // reduce + ELU -> d1s
            int base = (gwarp * 32 + lane) * 16;
            #pragma unroll
            for (int mt = 0; mt < 2; ++mt)
            #pragma unroll
            for (int nt = 0; nt < 2; ++nt) {
                int o = base + (mt * 2 + nt) * 4;
                float v0 = accd[mt][nt][0] + red[o];
                float v1 = accd[mt][nt][1] + red[o + 1];
                float v2 = accd[mt][nt][2] + red[o + 2];
                float v3 = accd[mt][nt][3] + red[o + 3];
                int col = nw * 16 + nt * 8 + 2 * tg;
                int row = mw * 32 + mt * 16 + gid;
                d1s[row * D1PAD + col]           = elu_f(v0);
                d1s[row * D1PAD + col + 1]       = elu_f(v1);
                d1s[(row + 8) * D1PAD + col]     = elu_f(v2);
                d1s[(row + 8) * D1PAD + col + 1] = elu_f(v3);
            }
        }
        __syncthreads();

        // ---- decode layer 2 + state update + output ----
        if (tid < BT * 3) {
            int b = tid / 3, j = tid - b * 3;
            const float* w = wd2_s + j * 64;
            const float* d = d1s + b * D1PAD;
            float sum = bd2_s[j];
            #pragma unroll
            for (int k = 0; k < 64; ++k)
                sum = fmaf(d[k], w[k], sum);
            float ns = st_s[tid] + sum;
            st_s[tid] = ns;
            out[(size_t)(bg0 + b) * (T_STEPS * 3) + t * 3 + j] = ns;
        }
        __syncthreads();
    }
}

// ----------------------------------------------------------------------------
extern "C" void kernel_launch(void* const* d_in, const int* in_sizes, int n_in,
                              void* d_out, int out_size)
{
    (void)in_sizes; (void)n_in; (void)out_size;
    const float* init_hidden = (const float*)d_in[0];
    const float* plan        = (const float*)d_in[1];
    const float* gate        = (const float*)d_in[2];
    const float* init_state  = (const float*)d_in[3];
    const float* Wp   = (const float*)d_in[4];
    const float* bp   = (const float*)d_in[5];
    const float* Ws   = (const float*)d_in[6];
    const float* bs   = (const float*)d_in[7];
    const float* W_ih = (const float*)d_in[8];
    const float* b_ih = (const float*)d_in[9];
    const float* W_hh = (const float*)d_in[10];
    const float* b_hh = (const float*)d_in[11];
    const float* Wd1  = (const float*)d_in[12];
    const float* bd1  = (const float*)d_in[13];
    const float* Wd2  = (const float*)d_in[14];
    const float* bd2  = (const float*)d_in[15];
    float* out = (float*)d_out;

    pack_kernel<<<(KTOT * NCOLS + 255) / 256, 256>>>(W_ih, W_hh, b_ih, b_hh, Wd1);

    const int smem_bytes = (A_U32 + BT * D1PAD + NCOLS + 1024
                            + D1 + 192 + 4 + BT * 3 + BT * 3 + BT) * 4;
    cudaFuncSetAttribute(decoder_kernel,
                         cudaFuncAttributeMaxDynamicSharedMemorySize, smem_bytes);
    decoder_kernel<<<B_TOTAL / BT, NTH, smem_bytes>>>(
        init_hidden, plan, gate, init_state,
        Wp, bp, Ws, bs, Wd2, bd2, bd1, out);
}